// round 12
// baseline (speedup 1.0000x reference)
#include <cuda_runtime.h>
#include <cuda_fp16.h>
#include <math.h>
#include <stdint.h>

// ---------------- problem constants ----------------
#define BATCH   64
#define SEQ     200
#define EMBED   64
#define VOCAB   95
#define LOUT    96
#define NCAPS   50
#define CAPSD   8
#define ODIM    16
#define NROUTE  3072
#define HID1    512
#define HID2    1024
#define NOUT    19000
#define CO      (NCAPS*ODIM)     // 800

// routing tiling
#define R_LOOP   16
#define GX       (NROUTE/R_LOOP)        // 192
#define BT       8                      // batches per block (2 quads x 4)
#define WROW     144                    // padded row (conflict-free LDS.128)
#define WTILE1   (NCAPS*WROW)           // 7200 floats per single-route tile
#define GEN_SMEM_FLOATS (2*WTILE1)      // 57.6 KB dynamic

// mlp3 tiling
#define M3_BT    32                     // batches per mlp3 block
#define M3_SMEM  (M3_BT*HID2*4)         // 128 KB

// ---------------- device scratch ----------------
__device__ float  g_u[BATCH * NROUTE * CAPSD];             // 6.3 MB
__device__ __half g_uhat_h[(size_t)BATCH * NROUTE * CO];   // 315 MB fp16 u_hat
__device__ float  g_S[BATCH * CO];                         // atomic accumulator
__device__ float  g_vsum[BATCH * CO];
__device__ float  g_h1[BATCH * HID1];
__device__ float  g_h2[BATCH * HID2];

// ---------------- half conversions ----------------
__device__ __forceinline__ uint2 f4_to_h4(float4 v) {
    __half2 h0 = __floats2half2_rn(v.x, v.y);
    __half2 h1 = __floats2half2_rn(v.z, v.w);
    uint2 r;
    r.x = *reinterpret_cast<uint32_t*>(&h0);
    r.y = *reinterpret_cast<uint32_t*>(&h1);
    return r;
}
__device__ __forceinline__ void h8_to_f8(uint4 r, float* f) {
    __half2 h0 = *reinterpret_cast<__half2*>(&r.x);
    __half2 h1 = *reinterpret_cast<__half2*>(&r.y);
    __half2 h2 = *reinterpret_cast<__half2*>(&r.z);
    __half2 h3 = *reinterpret_cast<__half2*>(&r.w);
    float2 a = __half22float2(h0), b = __half22float2(h1);
    float2 c = __half22float2(h2), d = __half22float2(h3);
    f[0]=a.x; f[1]=a.y; f[2]=b.x; f[3]=b.y;
    f[4]=c.x; f[5]=c.y; f[6]=d.x; f[7]=d.y;
}

// ---------------- zero g_S --------------------------------------------------
__global__ void zero_S_kernel() {
    int i = blockIdx.x * 256 + threadIdx.x;
    if (i < BATCH * CO) g_S[i] = 0.f;
}

// ---------------- kernel 1: embedding + conv1d + relu -> u ----------------
#define SEROW 60
__global__ __launch_bounds__(256, 2) void conv_embed_kernel(
    const int* __restrict__ x, const float* __restrict__ emb,
    const float* __restrict__ cw, const float* __restrict__ cb)
{
    __shared__ int   xs[56];
    __shared__ float se_t[EMBED * SEROW];

    const int l0 = blockIdx.x * 24;
    const int b  = blockIdx.y;
    const int t  = threadIdx.x;

    if (t < 55) xs[t] = x[b * SEQ + 2 * l0 + t];
    __syncthreads();
    for (int f = t; f < 55 * EMBED; f += 256) {
        int s = f >> 6, ic = f & 63;
        se_t[ic * SEROW + s] = emb[xs[s] * EMBED + ic];
    }
    __syncthreads();

    const int ch = t;
    float acc[24];
    {
        float bias = cb[ch];
        #pragma unroll
        for (int j = 0; j < 24; j++) acc[j] = bias;
    }

    const float* cwr = cw + (size_t)ch * (EMBED * 9);
    for (int ic0 = 0; ic0 < EMBED; ic0 += 4) {
        float w36[36];
        {
            const float4* wp = reinterpret_cast<const float4*>(cwr + ic0 * 9);
            #pragma unroll
            for (int q = 0; q < 9; q++) {
                float4 v = __ldg(wp + q);
                w36[4*q] = v.x; w36[4*q+1] = v.y; w36[4*q+2] = v.z; w36[4*q+3] = v.w;
            }
        }

        #pragma unroll
        for (int i4 = 0; i4 < 4; i4++) {
            const int ic = ic0 + i4;
            const float* w_r = w36 + i4 * 9;

            float se_r[56];
            const float4* rowp = reinterpret_cast<const float4*>(se_t + ic * SEROW);
            #pragma unroll
            for (int q = 0; q < 14; q++) {
                float4 v = rowp[q];
                se_r[4*q] = v.x; se_r[4*q+1] = v.y; se_r[4*q+2] = v.z; se_r[4*q+3] = v.w;
            }

            #pragma unroll
            for (int j = 0; j < 24; j++) {
                float a = acc[j];
                #pragma unroll
                for (int k = 0; k < 9; k++) a = fmaf(se_r[2 * j + k], w_r[k], a);
                acc[j] = a;
            }
        }
    }

    const int g = ch >> 3, i = ch & 7;
    #pragma unroll
    for (int j = 0; j < 24; j++) {
        int l = l0 + j;
        float v = acc[j];
        v = v > 0.f ? v : 0.f;
        g_u[((size_t)(b * NROUTE) + g * LOUT + l) * CAPSD + i] = v;
    }
}

// ---------------- gen: recompute u_hat, store fp16, atomic S0 --------------
__global__ __launch_bounds__(256, 2) void gen_kernel(const float* __restrict__ W)
{
    extern __shared__ float sm[];            // 2 x WTILE1
    __shared__ float su[BT][128];

    const int gx    = blockIdx.x;
    const int b0blk = blockIdx.y * BT;
    const int t     = threadIdx.x;
    const int warp  = t >> 5, lane = t & 31;
    const int qd    = warp >> 2;
    const int wq    = warp & 3;
    const int lane128 = wq * 32 + lane;
    const int rbase = gx * R_LOOP;

    const int v0 = lane128;
    const int v1 = 128 + lane128;
    const bool val1 = (v1 < 200);
    const int c0 = v0 >> 2;
    const int c1 = val1 ? (v1 >> 2) : 0;
    const int o40 = (v0 & 3) * 4;
    const int o41 = (v1 & 3) * 4;

    {
        int bk = t >> 5, f4 = t & 31;
        const float4* src = reinterpret_cast<const float4*>(
            g_u + ((size_t)((b0blk + bk) * NROUTE + rbase)) * CAPSD);
        reinterpret_cast<float4*>(su[bk])[f4] = src[f4];
    }

    float4 accA[4], accB[4];
    #pragma unroll
    for (int k = 0; k < 4; k++) {
        accA[k] = make_float4(0.f, 0.f, 0.f, 0.f);
        accB[k] = make_float4(0.f, 0.f, 0.f, 0.f);
    }

    for (int idx = t; idx < NCAPS * 32; idx += 256) {
        int c = idx >> 5, kk = idx & 31;
        const float* src = W + ((size_t)(c * NROUTE + rbase)) * 128 + kk * 4;
        float* dst = sm + c * WROW + kk * 4;
        uint32_t ds = (uint32_t)__cvta_generic_to_shared(dst);
        asm volatile("cp.async.ca.shared.global [%0], [%1], 16;\n" :: "r"(ds), "l"(src));
    }
    asm volatile("cp.async.commit_group;\n");

    for (int p = 0; p < R_LOOP; p++) {
        if (p + 1 < R_LOOP) {
            float* dstbase = sm + ((p + 1) & 1) * WTILE1;
            const int rp = rbase + p + 1;
            for (int idx = t; idx < NCAPS * 32; idx += 256) {
                int c = idx >> 5, kk = idx & 31;
                const float* src = W + ((size_t)(c * NROUTE + rp)) * 128 + kk * 4;
                float* dst = dstbase + c * WROW + kk * 4;
                uint32_t ds = (uint32_t)__cvta_generic_to_shared(dst);
                asm volatile("cp.async.ca.shared.global [%0], [%1], 16;\n" :: "r"(ds), "l"(src));
            }
            asm volatile("cp.async.commit_group;\n");
            asm volatile("cp.async.wait_group 1;\n");
        } else {
            asm volatile("cp.async.wait_group 0;\n");
        }
        __syncthreads();

        const float* wr = sm + (p & 1) * WTILE1;
        const int r = rbase + p;

        float u[4][8];
        #pragma unroll
        for (int k = 0; k < 4; k++) {
            const float4* up = reinterpret_cast<const float4*>(&su[qd * 4 + k][p * 8]);
            float4 a = up[0], b2 = up[1];
            u[k][0]=a.x; u[k][1]=a.y; u[k][2]=a.z; u[k][3]=a.w;
            u[k][4]=b2.x; u[k][5]=b2.y; u[k][6]=b2.z; u[k][7]=b2.w;
        }

        float4 uhA[4], uhB[4];
        {
            const float* wc = wr + c0 * WROW + o40;
            #pragma unroll
            for (int k = 0; k < 4; k++) uhA[k] = make_float4(0.f,0.f,0.f,0.f);
            #pragma unroll
            for (int i = 0; i < 8; i++) {
                float4 w4 = *reinterpret_cast<const float4*>(wc + i * 16);
                #pragma unroll
                for (int k = 0; k < 4; k++) {
                    uhA[k].x = fmaf(u[k][i], w4.x, uhA[k].x);
                    uhA[k].y = fmaf(u[k][i], w4.y, uhA[k].y);
                    uhA[k].z = fmaf(u[k][i], w4.z, uhA[k].z);
                    uhA[k].w = fmaf(u[k][i], w4.w, uhA[k].w);
                }
            }
        }
        {
            const float* wc = wr + c1 * WROW + o41;
            #pragma unroll
            for (int k = 0; k < 4; k++) uhB[k] = make_float4(0.f,0.f,0.f,0.f);
            #pragma unroll
            for (int i = 0; i < 8; i++) {
                float4 w4 = *reinterpret_cast<const float4*>(wc + i * 16);
                #pragma unroll
                for (int k = 0; k < 4; k++) {
                    uhB[k].x = fmaf(u[k][i], w4.x, uhB[k].x);
                    uhB[k].y = fmaf(u[k][i], w4.y, uhB[k].y);
                    uhB[k].z = fmaf(u[k][i], w4.z, uhB[k].z);
                    uhB[k].w = fmaf(u[k][i], w4.w, uhB[k].w);
                }
            }
        }

        #pragma unroll
        for (int k = 0; k < 4; k++) {
            size_t base = ((size_t)((b0blk + qd * 4 + k) * NROUTE) + r) * CO;
            *reinterpret_cast<uint2*>(g_uhat_h + base + 4 * (size_t)v0) = f4_to_h4(uhA[k]);
            if (val1)
                *reinterpret_cast<uint2*>(g_uhat_h + base + 4 * (size_t)v1) = f4_to_h4(uhB[k]);

            accA[k].x += uhA[k].x; accA[k].y += uhA[k].y;
            accA[k].z += uhA[k].z; accA[k].w += uhA[k].w;
            accB[k].x += uhB[k].x; accB[k].y += uhB[k].y;
            accB[k].z += uhB[k].z; accB[k].w += uhB[k].w;
        }
        __syncthreads();
    }

    // atomic accumulate S0 (REDG, spread addresses)
    #pragma unroll
    for (int k = 0; k < 4; k++) {
        int b = b0blk + qd * 4 + k;
        float* pb = g_S + b * CO;
        atomicAdd(pb + 4 * v0 + 0, accA[k].x);
        atomicAdd(pb + 4 * v0 + 1, accA[k].y);
        atomicAdd(pb + 4 * v0 + 2, accA[k].z);
        atomicAdd(pb + 4 * v0 + 3, accA[k].w);
        if (val1) {
            atomicAdd(pb + 4 * v1 + 0, accB[k].x);
            atomicAdd(pb + 4 * v1 + 1, accB[k].y);
            atomicAdd(pb + 4 * v1 + 2, accB[k].z);
            atomicAdd(pb + 4 * v1 + 3, accB[k].w);
        }
    }
}

// ---------------- routing read pass (warp-autonomous, atomic s) ------------
__global__ __launch_bounds__(256) void route_read_kernel()
{
    const int gx   = blockIdx.x;
    const int warp = threadIdx.x >> 5, lane = threadIdx.x & 31;
    const int b    = blockIdx.y * 8 + warp;
    const int rbase = gx * R_LOOP;
    const bool v3 = (lane < 4);

    float vs[4][8];
    #pragma unroll
    for (int s = 0; s < 4; s++) {
        int p = s * 32 + lane;
        if (s < 3 || v3) {
            float4 a = *reinterpret_cast<const float4*>(g_vsum + b * CO + 8 * p);
            float4 c = *reinterpret_cast<const float4*>(g_vsum + b * CO + 8 * p + 4);
            vs[s][0]=a.x; vs[s][1]=a.y; vs[s][2]=a.z; vs[s][3]=a.w;
            vs[s][4]=c.x; vs[s][5]=c.y; vs[s][6]=c.z; vs[s][7]=c.w;
        } else {
            #pragma unroll
            for (int j = 0; j < 8; j++) vs[s][j] = 0.f;
        }
    }

    float acc[4][8];
    #pragma unroll
    for (int s = 0; s < 4; s++)
        #pragma unroll
        for (int j = 0; j < 8; j++) acc[s][j] = 0.f;

    const size_t row0 = ((size_t)b * NROUTE + rbase) * CO;
    uint4 cur[4], nxt[4];
    const uint4 zero4 = make_uint4(0u, 0u, 0u, 0u);
    #pragma unroll
    for (int s = 0; s < 4; s++) {
        int p = s * 32 + lane;
        cur[s] = (s < 3 || v3)
            ? *reinterpret_cast<const uint4*>(g_uhat_h + row0 + 8 * (size_t)p)
            : zero4;
    }

    for (int roff = 0; roff < R_LOOP; roff++) {
        if (roff + 1 < R_LOOP) {
            size_t rowN = row0 + (size_t)(roff + 1) * CO;
            #pragma unroll
            for (int s = 0; s < 4; s++) {
                int p = s * 32 + lane;
                nxt[s] = (s < 3 || v3)
                    ? *reinterpret_cast<const uint4*>(g_uhat_h + rowN + 8 * (size_t)p)
                    : zero4;
            }
        }

        float uh[4][8];
        #pragma unroll
        for (int s = 0; s < 4; s++) h8_to_f8(cur[s], uh[s]);

        float d[4];
        #pragma unroll
        for (int s = 0; s < 4; s++) {
            float pdot = uh[s][0] * vs[s][0];
            #pragma unroll
            for (int j = 1; j < 8; j++) pdot = fmaf(uh[s][j], vs[s][j], pdot);
            pdot += __shfl_xor_sync(0xffffffffu, pdot, 1);
            d[s] = pdot;
        }
        if (!v3) d[3] = -1e30f;

        float m = fmaxf(fmaxf(d[0], d[1]), fmaxf(d[2], d[3]));
        #pragma unroll
        for (int off = 16; off >= 1; off >>= 1)
            m = fmaxf(m, __shfl_xor_sync(0xffffffffu, m, off));
        float e0 = __expf(d[0] - m);
        float e1 = __expf(d[1] - m);
        float e2 = __expf(d[2] - m);
        float e3 = v3 ? __expf(d[3] - m) : 0.f;
        float z = e0 + e1 + e2 + e3;
        #pragma unroll
        for (int off = 16; off >= 1; off >>= 1)
            z += __shfl_xor_sync(0xffffffffu, z, off);
        float invZ = 2.f / z;

        float cf[4] = { e0 * invZ, e1 * invZ, e2 * invZ, e3 * invZ };
        #pragma unroll
        for (int s = 0; s < 4; s++)
            #pragma unroll
            for (int j = 0; j < 8; j++)
                acc[s][j] = fmaf(cf[s], uh[s][j], acc[s][j]);

        #pragma unroll
        for (int s = 0; s < 4; s++) cur[s] = nxt[s];
    }

    // atomic accumulate s (REDG, spread addresses)
    float* pb = g_S + b * CO;
    #pragma unroll
    for (int s = 0; s < 4; s++) {
        int p = s * 32 + lane;
        if (s < 3 || v3) {
            #pragma unroll
            for (int j = 0; j < 8; j++)
                atomicAdd(pb + 8 * p + j, acc[s][j]);
        }
    }
}

// ---------------- squash: vsum = (add?vsum:0)+squash(s*mult); zero g_S -----
__global__ __launch_bounds__(256) void squash_kernel(float mult, int add_mode)
{
    int idx = blockIdx.x * blockDim.x + threadIdx.x;   // 12800
    int q = idx & 3, bc = idx >> 2;
    int b = bc / NCAPS, c = bc - b * NCAPS;

    float* sp = g_S + b * CO + c * ODIM + q * 4;
    float4 s = *reinterpret_cast<const float4*>(sp);
    *reinterpret_cast<float4*>(sp) = make_float4(0.f, 0.f, 0.f, 0.f);   // re-zero
    s.x *= mult; s.y *= mult; s.z *= mult; s.w *= mult;

    float n2 = s.x * s.x + s.y * s.y + s.z * s.z + s.w * s.w;
    n2 += __shfl_xor_sync(0xffffffffu, n2, 1);
    n2 += __shfl_xor_sync(0xffffffffu, n2, 2);
    float n = sqrtf(n2);
    float f = n2 / ((1.f + n2) * (n + 1e-8f));

    float* dst = g_vsum + b * CO + c * ODIM + q * 4;
    if (add_mode) {
        dst[0] += f * s.x; dst[1] += f * s.y; dst[2] += f * s.z; dst[3] += f * s.w;
    } else {
        dst[0] = f * s.x; dst[1] = f * s.y; dst[2] = f * s.z; dst[3] = f * s.w;
    }
}

// ---------------- final: squash(g_S), lengths, argmax + fused MLP layer 1 --
__global__ void final_kernel(float* __restrict__ out,
                             const float* __restrict__ w1, const float* __restrict__ b1)
{
    __shared__ float v_s[NCAPS * ODIM];
    __shared__ float len_s[NCAPS];
    __shared__ int am_s;

    const int b = blockIdx.x, t = threadIdx.x;
    if (t < 200) {
        const unsigned mask = ((t >> 5) == 6) ? 0xffu : 0xffffffffu;
        int c = t >> 2, q = t & 3;
        float4 s = *reinterpret_cast<const float4*>(g_S + b * CO + c * ODIM + q * 4);
        float n2 = s.x * s.x + s.y * s.y + s.z * s.z + s.w * s.w;
        n2 += __shfl_xor_sync(mask, n2, 1);
        n2 += __shfl_xor_sync(mask, n2, 2);
        float n = sqrtf(n2);
        float f = n2 / ((1.f + n2) * (n + 1e-8f));
        float* vd = v_s + c * ODIM + q * 4;
        vd[0] = f * s.x; vd[1] = f * s.y; vd[2] = f * s.z; vd[3] = f * s.w;
        if (q == 0) {
            float len = f * n;
            len_s[c] = len;
            out[b * NCAPS + c] = len;
        }
    }
    __syncthreads();
    if (t == 0) {
        int best = 0; float bl = len_s[0];
        for (int c = 1; c < NCAPS; c++) if (len_s[c] > bl) { bl = len_s[c]; best = c; }
        am_s = best;
    }
    __syncthreads();

    const int row0 = am_s * ODIM;
    #pragma unroll
    for (int h = 0; h < 2; h++) {
        int n = h * 256 + t;
        float acc = b1[n];
        #pragma unroll
        for (int o = 0; o < 16; o++)
            acc = fmaf(v_s[row0 + o], w1[(row0 + o) * HID1 + n], acc);
        g_h1[b * HID1 + n] = acc > 0.f ? acc : 0.f;
    }
}

// ---------------- MLP layer 2 ----------------------------------------------
__global__ __launch_bounds__(256) void mlp2_kernel(const float* __restrict__ w2,
                                                   const float* __restrict__ b2)
{
    __shared__ float h1s[8 * HID1];
    const int t = threadIdx.x;
    const int n = blockIdx.x * 256 + t;
    const int bb = blockIdx.y * 8;
    for (int f = t; f < 8 * HID1; f += 256) {
        int b8 = f >> 9, k = f & 511;
        h1s[f] = g_h1[(bb + b8) * HID1 + k];
    }
    __syncthreads();
    float acc[8];
    float bias = b2[n];
    #pragma unroll
    for (int b8 = 0; b8 < 8; b8++) acc[b8] = bias;
    #pragma unroll 4
    for (int k = 0; k < HID1; k++) {
        float w = w2[(size_t)k * HID2 + n];
        #pragma unroll
        for (int b8 = 0; b8 < 8; b8++) acc[b8] = fmaf(h1s[b8 * HID1 + k], w, acc[b8]);
    }
    #pragma unroll
    for (int b8 = 0; b8 < 8; b8++) {
        float v = acc[b8];
        g_h2[(bb + b8) * HID2 + n] = v > 0.f ? v : 0.f;
    }
}

// ---------------- MLP layer 3 + sigmoid -> recon ---------------------------
// grid (38, 2), 256 threads, 128 KB smem. Thread: 2 n-outputs x 32 batches.
__global__ __launch_bounds__(256) void mlp3_kernel(const float* __restrict__ w3,
                                                   const float* __restrict__ b3,
                                                   float* __restrict__ recon)
{
    extern __shared__ float h2s[];   // [32][1024]
    const int t = threadIdx.x;
    const int n0r = blockIdx.x * 512 + t;
    const int n1r = n0r + 256;
    const int bb = blockIdx.y * M3_BT;
    {
        const float4* src = reinterpret_cast<const float4*>(g_h2 + bb * HID2);
        float4* dst = reinterpret_cast<float4*>(h2s);
        for (int f = t; f < M3_BT * HID2 / 4; f += 256) dst[f] = src[f];
    }
    __syncthreads();

    const bool ok0 = (n0r < NOUT), ok1 = (n1r < NOUT);
    const int n0 = ok0 ? n0r : (NOUT - 1);
    const int n1 = ok1 ? n1r : (NOUT - 1);

    float acc0[M3_BT], acc1[M3_BT];
    {
        float bias0 = b3[n0], bias1 = b3[n1];
        #pragma unroll
        for (int bk = 0; bk < M3_BT; bk++) { acc0[bk] = bias0; acc1[bk] = bias1; }
    }

    for (int k0 = 0; k0 < HID2; k0 += 2) {
        const float* w3k = w3 + (size_t)k0 * NOUT;
        float wa0 = w3k[n0],        wb0 = w3k[n1];
        float wa1 = w3k[NOUT + n0], wb1 = w3k[NOUT + n1];
        #pragma unroll
        for (int bk = 0; bk < M3_BT; bk++) {
            float2 h = *reinterpret_cast<const float2*>(&h2s[bk * HID2 + k0]);
            float a0 = acc0[bk], a1 = acc1[bk];
            a0 = fmaf(h.x, wa0, a0); a1 = fmaf(h.x, wb0, a1);
            a0 = fmaf(h.y, wa1, a0); a1 = fmaf(h.y, wb1, a1);
            acc0[bk] = a0; acc1[bk] = a1;
        }
    }
    #pragma unroll
    for (int bk = 0; bk < M3_BT; bk++) {
        if (ok0) recon[(size_t)(bb + bk) * NOUT + n0r] = 1.f / (1.f + expf(-acc0[bk]));
        if (ok1) recon[(size_t)(bb + bk) * NOUT + n1r] = 1.f / (1.f + expf(-acc1[bk]));
    }
}

// ---------------- launch ----------------------------------------------------
extern "C" void kernel_launch(void* const* d_in, const int* in_sizes, int n_in,
                              void* d_out, int out_size)
{
    const int*   x      = (const int*)  d_in[0];
    const float* emb    = (const float*)d_in[1];
    const float* conv_w = (const float*)d_in[2];
    const float* conv_b = (const float*)d_in[3];
    const float* W      = (const float*)d_in[4];
    const float* w1     = (const float*)d_in[5];
    const float* b1     = (const float*)d_in[6];
    const float* w2     = (const float*)d_in[7];
    const float* b2     = (const float*)d_in[8];
    const float* w3     = (const float*)d_in[9];
    const float* b3     = (const float*)d_in[10];
    float* out = (float*)d_out;
    float* recon = out + ((size_t)out_size - (size_t)BATCH * NOUT);

    const int gen_smem = GEN_SMEM_FLOATS * (int)sizeof(float);   // 57.6 KB

    static int attr_done = 0;
    if (!attr_done) {
        cudaFuncSetAttribute(mlp3_kernel, cudaFuncAttributeMaxDynamicSharedMemorySize,
                             M3_SMEM);
        cudaFuncSetAttribute(gen_kernel, cudaFuncAttributeMaxDynamicSharedMemorySize,
                             gen_smem);
        attr_done = 1;
    }

    // 1. conv/embed -> u  +  zero g_S (concurrent, independent)
    conv_embed_kernel<<<dim3(4, BATCH), 256>>>(x, emb, conv_w, conv_b);
    zero_S_kernel<<<(BATCH * CO + 255) / 256, 256>>>();

    // 2. gen: u_hat fp16 + S0 atomics
    gen_kernel<<<dim3(GX, BATCH / BT), 256, gen_smem>>>(W);

    // 3. v0 = squash(S0/50); vsum = v0; g_S re-zeroed
    squash_kernel<<<(BATCH * NCAPS * 4) / 256, 256>>>(1.f / (float)NCAPS, 0);

    // 4. pass 1: s1 atomics (softmax vs v0)
    route_read_kernel<<<dim3(GX, BATCH / 8), 256>>>();

    // 5. v1 = squash(s1); vsum += v1; g_S re-zeroed
    squash_kernel<<<(BATCH * NCAPS * 4) / 256, 256>>>(1.f, 1);

    // 6. pass 2: s2 atomics (softmax vs v0+v1)
    route_read_kernel<<<dim3(GX, BATCH / 8), 256>>>();

    // 7. final v, lengths, argmax + MLP layer 1
    final_kernel<<<BATCH, 256>>>(out, w1, b1);

    // 8. MLP layers 2,3 + sigmoid
    mlp2_kernel<<<dim3(HID2 / 256, BATCH / 8), 256>>>(w2, b2);
    mlp3_kernel<<<dim3((NOUT + 511) / 512, BATCH / M3_BT), 256, M3_SMEM>>>(w3, b3, recon);
}

// round 13
// speedup vs baseline: 1.8988x; 1.8988x over previous
#include <cuda_runtime.h>
#include <cuda_fp16.h>
#include <math.h>
#include <stdint.h>

// ---------------- problem constants ----------------
#define BATCH   64
#define SEQ     200
#define EMBED   64
#define VOCAB   95
#define LOUT    96
#define NCAPS   50
#define CAPSD   8
#define ODIM    16
#define NROUTE  3072
#define HID1    512
#define HID2    1024
#define NOUT    19000
#define CO      (NCAPS*ODIM)     // 800

// routing tiling
#define R_LOOP   16
#define GX       (NROUTE/R_LOOP)        // 192
#define BT       8                      // batches per block (2 quads x 4)
#define WROW     144                    // padded row (conflict-free LDS.128)
#define WTILE1   (NCAPS*WROW)           // 7200 floats per single-route tile
#define GEN_SMEM_FLOATS (2*WTILE1)      // 57.6 KB dynamic

// ---------------- device scratch ----------------
__device__ float  g_u[BATCH * NROUTE * CAPSD];             // 6.3 MB
__device__ __half g_uhat_h[(size_t)BATCH * NROUTE * CO];   // 315 MB fp16 u_hat
__device__ float  g_Spart[(size_t)BATCH * GX * CO];        // [b][gx][CO] 39.3 MB
__device__ float  g_vsum[BATCH * CO];
__device__ float  g_h1[BATCH * HID1];
__device__ float  g_h2[BATCH * HID2];

// ---------------- half conversions ----------------
__device__ __forceinline__ uint2 f4_to_h4(float4 v) {
    __half2 h0 = __floats2half2_rn(v.x, v.y);
    __half2 h1 = __floats2half2_rn(v.z, v.w);
    uint2 r;
    r.x = *reinterpret_cast<uint32_t*>(&h0);
    r.y = *reinterpret_cast<uint32_t*>(&h1);
    return r;
}
__device__ __forceinline__ void h8_to_f8(uint4 r, float* f) {
    __half2 h0 = *reinterpret_cast<__half2*>(&r.x);
    __half2 h1 = *reinterpret_cast<__half2*>(&r.y);
    __half2 h2 = *reinterpret_cast<__half2*>(&r.z);
    __half2 h3 = *reinterpret_cast<__half2*>(&r.w);
    float2 a = __half22float2(h0), b = __half22float2(h1);
    float2 c = __half22float2(h2), d = __half22float2(h3);
    f[0]=a.x; f[1]=a.y; f[2]=b.x; f[3]=b.y;
    f[4]=c.x; f[5]=c.y; f[6]=d.x; f[7]=d.y;
}

// ---------------- kernel 1: embedding + conv1d + relu -> u ----------------
#define SEROW 60
__global__ __launch_bounds__(256, 2) void conv_embed_kernel(
    const int* __restrict__ x, const float* __restrict__ emb,
    const float* __restrict__ cw, const float* __restrict__ cb)
{
    __shared__ int   xs[56];
    __shared__ float se_t[EMBED * SEROW];

    const int l0 = blockIdx.x * 24;
    const int b  = blockIdx.y;
    const int t  = threadIdx.x;

    if (t < 55) xs[t] = x[b * SEQ + 2 * l0 + t];
    __syncthreads();
    for (int f = t; f < 55 * EMBED; f += 256) {
        int s = f >> 6, ic = f & 63;
        se_t[ic * SEROW + s] = emb[xs[s] * EMBED + ic];
    }
    __syncthreads();

    const int ch = t;
    float acc[24];
    {
        float bias = cb[ch];
        #pragma unroll
        for (int j = 0; j < 24; j++) acc[j] = bias;
    }

    const float* cwr = cw + (size_t)ch * (EMBED * 9);
    for (int ic0 = 0; ic0 < EMBED; ic0 += 4) {
        float w36[36];
        {
            const float4* wp = reinterpret_cast<const float4*>(cwr + ic0 * 9);
            #pragma unroll
            for (int q = 0; q < 9; q++) {
                float4 v = __ldg(wp + q);
                w36[4*q] = v.x; w36[4*q+1] = v.y; w36[4*q+2] = v.z; w36[4*q+3] = v.w;
            }
        }

        #pragma unroll
        for (int i4 = 0; i4 < 4; i4++) {
            const int ic = ic0 + i4;
            const float* w_r = w36 + i4 * 9;

            float se_r[56];
            const float4* rowp = reinterpret_cast<const float4*>(se_t + ic * SEROW);
            #pragma unroll
            for (int q = 0; q < 14; q++) {
                float4 v = rowp[q];
                se_r[4*q] = v.x; se_r[4*q+1] = v.y; se_r[4*q+2] = v.z; se_r[4*q+3] = v.w;
            }

            #pragma unroll
            for (int j = 0; j < 24; j++) {
                float a = acc[j];
                #pragma unroll
                for (int k = 0; k < 9; k++) a = fmaf(se_r[2 * j + k], w_r[k], a);
                acc[j] = a;
            }
        }
    }

    const int g = ch >> 3, i = ch & 7;
    #pragma unroll
    for (int j = 0; j < 24; j++) {
        int l = l0 + j;
        float v = acc[j];
        v = v > 0.f ? v : 0.f;
        g_u[((size_t)(b * NROUTE) + g * LOUT + l) * CAPSD + i] = v;
    }
}

// ---------------- gen: recompute u_hat, store fp16, S0 partials ------------
__global__ __launch_bounds__(256, 2) void gen_kernel(const float* __restrict__ W)
{
    extern __shared__ float sm[];            // 2 x WTILE1
    __shared__ float su[BT][128];

    const int gx    = blockIdx.x;
    const int b0blk = blockIdx.y * BT;
    const int t     = threadIdx.x;
    const int warp  = t >> 5, lane = t & 31;
    const int qd    = warp >> 2;
    const int wq    = warp & 3;
    const int lane128 = wq * 32 + lane;
    const int rbase = gx * R_LOOP;

    const int v0 = lane128;
    const int v1 = 128 + lane128;
    const bool val1 = (v1 < 200);
    const int c0 = v0 >> 2;
    const int c1 = val1 ? (v1 >> 2) : 0;
    const int o40 = (v0 & 3) * 4;
    const int o41 = (v1 & 3) * 4;

    {
        int bk = t >> 5, f4 = t & 31;
        const float4* src = reinterpret_cast<const float4*>(
            g_u + ((size_t)((b0blk + bk) * NROUTE + rbase)) * CAPSD);
        reinterpret_cast<float4*>(su[bk])[f4] = src[f4];
    }

    float4 accA[4], accB[4];
    #pragma unroll
    for (int k = 0; k < 4; k++) {
        accA[k] = make_float4(0.f, 0.f, 0.f, 0.f);
        accB[k] = make_float4(0.f, 0.f, 0.f, 0.f);
    }

    for (int idx = t; idx < NCAPS * 32; idx += 256) {
        int c = idx >> 5, kk = idx & 31;
        const float* src = W + ((size_t)(c * NROUTE + rbase)) * 128 + kk * 4;
        float* dst = sm + c * WROW + kk * 4;
        uint32_t ds = (uint32_t)__cvta_generic_to_shared(dst);
        asm volatile("cp.async.ca.shared.global [%0], [%1], 16;\n" :: "r"(ds), "l"(src));
    }
    asm volatile("cp.async.commit_group;\n");

    for (int p = 0; p < R_LOOP; p++) {
        if (p + 1 < R_LOOP) {
            float* dstbase = sm + ((p + 1) & 1) * WTILE1;
            const int rp = rbase + p + 1;
            for (int idx = t; idx < NCAPS * 32; idx += 256) {
                int c = idx >> 5, kk = idx & 31;
                const float* src = W + ((size_t)(c * NROUTE + rp)) * 128 + kk * 4;
                float* dst = dstbase + c * WROW + kk * 4;
                uint32_t ds = (uint32_t)__cvta_generic_to_shared(dst);
                asm volatile("cp.async.ca.shared.global [%0], [%1], 16;\n" :: "r"(ds), "l"(src));
            }
            asm volatile("cp.async.commit_group;\n");
            asm volatile("cp.async.wait_group 1;\n");
        } else {
            asm volatile("cp.async.wait_group 0;\n");
        }
        __syncthreads();

        const float* wr = sm + (p & 1) * WTILE1;
        const int r = rbase + p;

        float u[4][8];
        #pragma unroll
        for (int k = 0; k < 4; k++) {
            const float4* up = reinterpret_cast<const float4*>(&su[qd * 4 + k][p * 8]);
            float4 a = up[0], b2 = up[1];
            u[k][0]=a.x; u[k][1]=a.y; u[k][2]=a.z; u[k][3]=a.w;
            u[k][4]=b2.x; u[k][5]=b2.y; u[k][6]=b2.z; u[k][7]=b2.w;
        }

        float4 uhA[4], uhB[4];
        {
            const float* wc = wr + c0 * WROW + o40;
            #pragma unroll
            for (int k = 0; k < 4; k++) uhA[k] = make_float4(0.f,0.f,0.f,0.f);
            #pragma unroll
            for (int i = 0; i < 8; i++) {
                float4 w4 = *reinterpret_cast<const float4*>(wc + i * 16);
                #pragma unroll
                for (int k = 0; k < 4; k++) {
                    uhA[k].x = fmaf(u[k][i], w4.x, uhA[k].x);
                    uhA[k].y = fmaf(u[k][i], w4.y, uhA[k].y);
                    uhA[k].z = fmaf(u[k][i], w4.z, uhA[k].z);
                    uhA[k].w = fmaf(u[k][i], w4.w, uhA[k].w);
                }
            }
        }
        {
            const float* wc = wr + c1 * WROW + o41;
            #pragma unroll
            for (int k = 0; k < 4; k++) uhB[k] = make_float4(0.f,0.f,0.f,0.f);
            #pragma unroll
            for (int i = 0; i < 8; i++) {
                float4 w4 = *reinterpret_cast<const float4*>(wc + i * 16);
                #pragma unroll
                for (int k = 0; k < 4; k++) {
                    uhB[k].x = fmaf(u[k][i], w4.x, uhB[k].x);
                    uhB[k].y = fmaf(u[k][i], w4.y, uhB[k].y);
                    uhB[k].z = fmaf(u[k][i], w4.z, uhB[k].z);
                    uhB[k].w = fmaf(u[k][i], w4.w, uhB[k].w);
                }
            }
        }

        #pragma unroll
        for (int k = 0; k < 4; k++) {
            size_t base = ((size_t)((b0blk + qd * 4 + k) * NROUTE) + r) * CO;
            *reinterpret_cast<uint2*>(g_uhat_h + base + 4 * (size_t)v0) = f4_to_h4(uhA[k]);
            if (val1)
                *reinterpret_cast<uint2*>(g_uhat_h + base + 4 * (size_t)v1) = f4_to_h4(uhB[k]);

            accA[k].x += uhA[k].x; accA[k].y += uhA[k].y;
            accA[k].z += uhA[k].z; accA[k].w += uhA[k].w;
            accB[k].x += uhB[k].x; accB[k].y += uhB[k].y;
            accB[k].z += uhB[k].z; accB[k].w += uhB[k].w;
        }
        __syncthreads();
    }

    #pragma unroll
    for (int k = 0; k < 4; k++) {
        int b = b0blk + qd * 4 + k;
        float* pb = g_Spart + ((size_t)b * GX + gx) * CO;
        *reinterpret_cast<float4*>(pb + 4 * v0) = accA[k];
        if (val1) *reinterpret_cast<float4*>(pb + 4 * v1) = accB[k];
    }
}

// ---------------- routing read pass (warp-autonomous, barrier-free) --------
__global__ __launch_bounds__(256) void route_read_kernel()
{
    const int gx   = blockIdx.x;
    const int warp = threadIdx.x >> 5, lane = threadIdx.x & 31;
    const int b    = blockIdx.y * 8 + warp;
    const int rbase = gx * R_LOOP;
    const bool v3 = (lane < 4);

    float vs[4][8];
    #pragma unroll
    for (int s = 0; s < 4; s++) {
        int p = s * 32 + lane;
        if (s < 3 || v3) {
            float4 a = *reinterpret_cast<const float4*>(g_vsum + b * CO + 8 * p);
            float4 c = *reinterpret_cast<const float4*>(g_vsum + b * CO + 8 * p + 4);
            vs[s][0]=a.x; vs[s][1]=a.y; vs[s][2]=a.z; vs[s][3]=a.w;
            vs[s][4]=c.x; vs[s][5]=c.y; vs[s][6]=c.z; vs[s][7]=c.w;
        } else {
            #pragma unroll
            for (int j = 0; j < 8; j++) vs[s][j] = 0.f;
        }
    }

    float acc[4][8];
    #pragma unroll
    for (int s = 0; s < 4; s++)
        #pragma unroll
        for (int j = 0; j < 8; j++) acc[s][j] = 0.f;

    const size_t row0 = ((size_t)b * NROUTE + rbase) * CO;
    uint4 cur[4], nxt[4];
    const uint4 zero4 = make_uint4(0u, 0u, 0u, 0u);
    #pragma unroll
    for (int s = 0; s < 4; s++) {
        int p = s * 32 + lane;
        cur[s] = (s < 3 || v3)
            ? *reinterpret_cast<const uint4*>(g_uhat_h + row0 + 8 * (size_t)p)
            : zero4;
    }

    for (int roff = 0; roff < R_LOOP; roff++) {
        if (roff + 1 < R_LOOP) {
            size_t rowN = row0 + (size_t)(roff + 1) * CO;
            #pragma unroll
            for (int s = 0; s < 4; s++) {
                int p = s * 32 + lane;
                nxt[s] = (s < 3 || v3)
                    ? *reinterpret_cast<const uint4*>(g_uhat_h + rowN + 8 * (size_t)p)
                    : zero4;
            }
        }

        float uh[4][8];
        #pragma unroll
        for (int s = 0; s < 4; s++) h8_to_f8(cur[s], uh[s]);

        float d[4];
        #pragma unroll
        for (int s = 0; s < 4; s++) {
            float pdot = uh[s][0] * vs[s][0];
            #pragma unroll
            for (int j = 1; j < 8; j++) pdot = fmaf(uh[s][j], vs[s][j], pdot);
            pdot += __shfl_xor_sync(0xffffffffu, pdot, 1);
            d[s] = pdot;
        }
        if (!v3) d[3] = -1e30f;

        float m = fmaxf(fmaxf(d[0], d[1]), fmaxf(d[2], d[3]));
        #pragma unroll
        for (int off = 16; off >= 1; off >>= 1)
            m = fmaxf(m, __shfl_xor_sync(0xffffffffu, m, off));
        float e0 = __expf(d[0] - m);
        float e1 = __expf(d[1] - m);
        float e2 = __expf(d[2] - m);
        float e3 = v3 ? __expf(d[3] - m) : 0.f;
        float z = e0 + e1 + e2 + e3;
        #pragma unroll
        for (int off = 16; off >= 1; off >>= 1)
            z += __shfl_xor_sync(0xffffffffu, z, off);
        float invZ = 2.f / z;

        float cf[4] = { e0 * invZ, e1 * invZ, e2 * invZ, e3 * invZ };
        #pragma unroll
        for (int s = 0; s < 4; s++)
            #pragma unroll
            for (int j = 0; j < 8; j++)
                acc[s][j] = fmaf(cf[s], uh[s][j], acc[s][j]);

        #pragma unroll
        for (int s = 0; s < 4; s++) cur[s] = nxt[s];
    }

    float* pb = g_Spart + ((size_t)b * GX + gx) * CO;
    #pragma unroll
    for (int s = 0; s < 4; s++) {
        int p = s * 32 + lane;
        if (s < 3 || v3) {
            *reinterpret_cast<float4*>(pb + 8 * p) =
                make_float4(acc[s][0], acc[s][1], acc[s][2], acc[s][3]);
            *reinterpret_cast<float4*>(pb + 8 * p + 4) =
                make_float4(acc[s][4], acc[s][5], acc[s][6], acc[s][7]);
        }
    }
}

// ---------------- fused gx-reduce + squash ---------------------------------
// vsum = (add? vsum : 0) + squash(sum_gx(Spart)*mult). 50 blocks x 256.
// Warp covers 128 consecutive floats per gx step -> coalesced 512B reads.
__global__ __launch_bounds__(256) void squash_partials_kernel(float mult, int add_mode)
{
    int idx = blockIdx.x * blockDim.x + threadIdx.x;   // 12800
    int q = idx & 3, bc = idx >> 2;
    int b = bc / NCAPS, c = bc - b * NCAPS;

    const float* base = g_Spart + (size_t)b * GX * CO + c * ODIM + q * 4;
    float4 s = make_float4(0.f, 0.f, 0.f, 0.f);
    #pragma unroll 8
    for (int gx = 0; gx < GX; gx++) {
        float4 p = *reinterpret_cast<const float4*>(base + (size_t)gx * CO);
        s.x += p.x; s.y += p.y; s.z += p.z; s.w += p.w;
    }
    s.x *= mult; s.y *= mult; s.z *= mult; s.w *= mult;

    float n2 = s.x * s.x + s.y * s.y + s.z * s.z + s.w * s.w;
    n2 += __shfl_xor_sync(0xffffffffu, n2, 1);
    n2 += __shfl_xor_sync(0xffffffffu, n2, 2);
    float n = sqrtf(n2);
    float f = n2 / ((1.f + n2) * (n + 1e-8f));

    float* dst = g_vsum + b * CO + c * ODIM + q * 4;
    if (add_mode) {
        dst[0] += f * s.x; dst[1] += f * s.y; dst[2] += f * s.z; dst[3] += f * s.w;
    } else {
        dst[0] = f * s.x; dst[1] = f * s.y; dst[2] = f * s.z; dst[3] = f * s.w;
    }
}

// ---------------- final: inline reduce, squash, argmax + fused MLP layer 1 -
__global__ void final_kernel(float* __restrict__ out,
                             const float* __restrict__ w1, const float* __restrict__ b1)
{
    __shared__ float v_s[NCAPS * ODIM];
    __shared__ float len_s[NCAPS];
    __shared__ int am_s;

    const int b = blockIdx.x, t = threadIdx.x;
    if (t < 200) {
        const unsigned mask = ((t >> 5) == 6) ? 0xffu : 0xffffffffu;
        int c = t >> 2, q = t & 3;
        const float* base = g_Spart + (size_t)b * GX * CO + c * ODIM + q * 4;
        float4 s = make_float4(0.f, 0.f, 0.f, 0.f);
        #pragma unroll 8
        for (int gx = 0; gx < GX; gx++) {
            float4 p = *reinterpret_cast<const float4*>(base + (size_t)gx * CO);
            s.x += p.x; s.y += p.y; s.z += p.z; s.w += p.w;
        }
        float n2 = s.x * s.x + s.y * s.y + s.z * s.z + s.w * s.w;
        n2 += __shfl_xor_sync(mask, n2, 1);
        n2 += __shfl_xor_sync(mask, n2, 2);
        float n = sqrtf(n2);
        float f = n2 / ((1.f + n2) * (n + 1e-8f));
        float* vd = v_s + c * ODIM + q * 4;
        vd[0] = f * s.x; vd[1] = f * s.y; vd[2] = f * s.z; vd[3] = f * s.w;
        if (q == 0) {
            float len = f * n;
            len_s[c] = len;
            out[b * NCAPS + c] = len;
        }
    }
    __syncthreads();
    if (t == 0) {
        int best = 0; float bl = len_s[0];
        for (int c = 1; c < NCAPS; c++) if (len_s[c] > bl) { bl = len_s[c]; best = c; }
        am_s = best;
    }
    __syncthreads();

    const int row0 = am_s * ODIM;
    #pragma unroll
    for (int h = 0; h < 2; h++) {
        int n = h * 256 + t;
        float acc = b1[n];
        #pragma unroll
        for (int o = 0; o < 16; o++)
            acc = fmaf(v_s[row0 + o], w1[(row0 + o) * HID1 + n], acc);
        g_h1[b * HID1 + n] = acc > 0.f ? acc : 0.f;
    }
}

// ---------------- MLP layer 2 ----------------------------------------------
__global__ __launch_bounds__(256) void mlp2_kernel(const float* __restrict__ w2,
                                                   const float* __restrict__ b2)
{
    __shared__ float h1s[8 * HID1];
    const int t = threadIdx.x;
    const int n = blockIdx.x * 256 + t;
    const int bb = blockIdx.y * 8;
    for (int f = t; f < 8 * HID1; f += 256) {
        int b8 = f >> 9, k = f & 511;
        h1s[f] = g_h1[(bb + b8) * HID1 + k];
    }
    __syncthreads();
    float acc[8];
    float bias = b2[n];
    #pragma unroll
    for (int b8 = 0; b8 < 8; b8++) acc[b8] = bias;
    #pragma unroll 4
    for (int k = 0; k < HID1; k++) {
        float w = w2[(size_t)k * HID2 + n];
        #pragma unroll
        for (int b8 = 0; b8 < 8; b8++) acc[b8] = fmaf(h1s[b8 * HID1 + k], w, acc[b8]);
    }
    #pragma unroll
    for (int b8 = 0; b8 < 8; b8++) {
        float v = acc[b8];
        g_h2[(bb + b8) * HID2 + n] = v > 0.f ? v : 0.f;
    }
}

// ---------------- MLP layer 3 + sigmoid -> recon ---------------------------
// grid (38, 4), 256 threads, 64 KB smem. Each thread: 2 n-outputs x 16 batches.
__global__ __launch_bounds__(256) void mlp3_kernel(const float* __restrict__ w3,
                                                   const float* __restrict__ b3,
                                                   float* __restrict__ recon)
{
    extern __shared__ float h2s[];   // [16][1024]
    const int t = threadIdx.x;
    const int n0r = blockIdx.x * 512 + t;
    const int n1r = n0r + 256;
    const int bb = blockIdx.y * 16;
    {
        const float4* src = reinterpret_cast<const float4*>(g_h2 + bb * HID2);
        float4* dst = reinterpret_cast<float4*>(h2s);
        for (int f = t; f < 16 * HID2 / 4; f += 256) dst[f] = src[f];
    }
    __syncthreads();

    const bool ok0 = (n0r < NOUT), ok1 = (n1r < NOUT);
    const int n0 = ok0 ? n0r : (NOUT - 1);
    const int n1 = ok1 ? n1r : (NOUT - 1);

    float acc0[16], acc1[16];
    {
        float bias0 = b3[n0], bias1 = b3[n1];
        #pragma unroll
        for (int b16 = 0; b16 < 16; b16++) { acc0[b16] = bias0; acc1[b16] = bias1; }
    }

    for (int k0 = 0; k0 < HID2; k0 += 4) {
        const float* w3k = w3 + (size_t)k0 * NOUT;
        float wa0 = w3k[n0],            wb0 = w3k[n1];
        float wa1 = w3k[NOUT + n0],     wb1 = w3k[NOUT + n1];
        float wa2 = w3k[2 * NOUT + n0], wb2 = w3k[2 * NOUT + n1];
        float wa3 = w3k[3 * NOUT + n0], wb3 = w3k[3 * NOUT + n1];
        #pragma unroll
        for (int b16 = 0; b16 < 16; b16++) {
            float4 h = *reinterpret_cast<const float4*>(&h2s[b16 * HID2 + k0]);
            float a0 = acc0[b16], a1 = acc1[b16];
            a0 = fmaf(h.x, wa0, a0); a1 = fmaf(h.x, wb0, a1);
            a0 = fmaf(h.y, wa1, a0); a1 = fmaf(h.y, wb1, a1);
            a0 = fmaf(h.z, wa2, a0); a1 = fmaf(h.z, wb2, a1);
            a0 = fmaf(h.w, wa3, a0); a1 = fmaf(h.w, wb3, a1);
            acc0[b16] = a0; acc1[b16] = a1;
        }
    }
    #pragma unroll
    for (int b16 = 0; b16 < 16; b16++) {
        if (ok0) recon[(size_t)(bb + b16) * NOUT + n0r] = 1.f / (1.f + expf(-acc0[b16]));
        if (ok1) recon[(size_t)(bb + b16) * NOUT + n1r] = 1.f / (1.f + expf(-acc1[b16]));
    }
}

// ---------------- launch ----------------------------------------------------
extern "C" void kernel_launch(void* const* d_in, const int* in_sizes, int n_in,
                              void* d_out, int out_size)
{
    const int*   x      = (const int*)  d_in[0];
    const float* emb    = (const float*)d_in[1];
    const float* conv_w = (const float*)d_in[2];
    const float* conv_b = (const float*)d_in[3];
    const float* W      = (const float*)d_in[4];
    const float* w1     = (const float*)d_in[5];
    const float* b1     = (const float*)d_in[6];
    const float* w2     = (const float*)d_in[7];
    const float* b2     = (const float*)d_in[8];
    const float* w3     = (const float*)d_in[9];
    const float* b3     = (const float*)d_in[10];
    float* out = (float*)d_out;
    float* recon = out + ((size_t)out_size - (size_t)BATCH * NOUT);

    const int gen_smem = GEN_SMEM_FLOATS * (int)sizeof(float);   // 57.6 KB

    static int attr_done = 0;
    if (!attr_done) {
        cudaFuncSetAttribute(mlp3_kernel, cudaFuncAttributeMaxDynamicSharedMemorySize,
                             16 * HID2 * sizeof(float));
        cudaFuncSetAttribute(gen_kernel, cudaFuncAttributeMaxDynamicSharedMemorySize,
                             gen_smem);
        attr_done = 1;
    }

    // 1. conv/embed -> u
    conv_embed_kernel<<<dim3(4, BATCH), 256>>>(x, emb, conv_w, conv_b);

    // 2. gen: u_hat fp16 + S0 partials (2 CTAs/SM)
    gen_kernel<<<dim3(GX, BATCH / BT), 256, gen_smem>>>(W);

    // 3. v0 = squash(reduce(S0)/50); vsum = v0   (fused reduce)
    squash_partials_kernel<<<(BATCH * NCAPS * 4) / 256, 256>>>(1.f / (float)NCAPS, 0);

    // 4. pass 1: s1 partials (softmax vs v0)
    route_read_kernel<<<dim3(GX, BATCH / 8), 256>>>();

    // 5. v1 = squash(reduce(s1)); vsum += v1
    squash_partials_kernel<<<(BATCH * NCAPS * 4) / 256, 256>>>(1.f, 1);

    // 6. pass 2: s2 partials (softmax vs v0+v1)
    route_read_kernel<<<dim3(GX, BATCH / 8), 256>>>();

    // 7. final: inline reduce, v, lengths, argmax + MLP layer 1
    final_kernel<<<BATCH, 256>>>(out, w1, b1);

    // 8. MLP layers 2,3 + sigmoid
    mlp2_kernel<<<dim3(HID2 / 256, BATCH / 8), 256>>>(w2, b2);
    mlp3_kernel<<<dim3((NOUT + 511) / 512, BATCH / 16), 256,
                 16 * HID2 * sizeof(float)>>>(w3, b3, recon);
}

// round 15
// speedup vs baseline: 2.0593x; 1.0845x over previous
#include <cuda_runtime.h>
#include <cuda_fp16.h>
#include <math.h>
#include <stdint.h>

// ---------------- problem constants ----------------
#define BATCH   64
#define SEQ     200
#define EMBED   64
#define VOCAB   95
#define LOUT    96
#define NCAPS   50
#define CAPSD   8
#define ODIM    16
#define NROUTE  3072
#define HID1    512
#define HID2    1024
#define NOUT    19000
#define CO      (NCAPS*ODIM)     // 800

// routing tiling
#define R_LOOP   16
#define GX       (NROUTE/R_LOOP)        // 192
#define BT       8                      // batches per block (2 quads x 4)
#define WROW     144                    // padded row (conflict-free LDS.128)
#define WTILE1   (NCAPS*WROW)           // 7200 floats per single-route tile
#define GEN_SMEM_FLOATS (2*WTILE1)      // 57.6 KB dynamic

// ---------------- device scratch ----------------
__device__ float  g_u[BATCH * NROUTE * CAPSD];             // 6.3 MB
__device__ __half g_uhat_h[(size_t)BATCH * NROUTE * CO];   // 315 MB fp16 u_hat
__device__ float  g_Spart[(size_t)BATCH * GX * CO];        // [b][gx][CO] 39.3 MB
__device__ float  g_S[BATCH * CO];
__device__ float  g_vsum[BATCH * CO];
__device__ float  g_h1[BATCH * HID1];
__device__ float  g_h2[BATCH * HID2];

// ---------------- half conversions ----------------
__device__ __forceinline__ uint2 f4_to_h4(float4 v) {
    __half2 h0 = __floats2half2_rn(v.x, v.y);
    __half2 h1 = __floats2half2_rn(v.z, v.w);
    uint2 r;
    r.x = *reinterpret_cast<uint32_t*>(&h0);
    r.y = *reinterpret_cast<uint32_t*>(&h1);
    return r;
}
__device__ __forceinline__ void h8_to_f8(uint4 r, float* f) {
    __half2 h0 = *reinterpret_cast<__half2*>(&r.x);
    __half2 h1 = *reinterpret_cast<__half2*>(&r.y);
    __half2 h2 = *reinterpret_cast<__half2*>(&r.z);
    __half2 h3 = *reinterpret_cast<__half2*>(&r.w);
    float2 a = __half22float2(h0), b = __half22float2(h1);
    float2 c = __half22float2(h2), d = __half22float2(h3);
    f[0]=a.x; f[1]=a.y; f[2]=b.x; f[3]=b.y;
    f[4]=c.x; f[5]=c.y; f[6]=d.x; f[7]=d.y;
}

// ---------------- kernel 1: embedding + conv1d + relu -> u ----------------
#define SEROW 60
__global__ __launch_bounds__(256, 2) void conv_embed_kernel(
    const int* __restrict__ x, const float* __restrict__ emb,
    const float* __restrict__ cw, const float* __restrict__ cb)
{
    __shared__ int   xs[56];
    __shared__ float se_t[EMBED * SEROW];

    const int l0 = blockIdx.x * 24;
    const int b  = blockIdx.y;
    const int t  = threadIdx.x;

    if (t < 55) xs[t] = x[b * SEQ + 2 * l0 + t];
    __syncthreads();
    for (int f = t; f < 55 * EMBED; f += 256) {
        int s = f >> 6, ic = f & 63;
        se_t[ic * SEROW + s] = emb[xs[s] * EMBED + ic];
    }
    __syncthreads();

    const int ch = t;
    float acc[24];
    {
        float bias = cb[ch];
        #pragma unroll
        for (int j = 0; j < 24; j++) acc[j] = bias;
    }

    const float* cwr = cw + (size_t)ch * (EMBED * 9);
    for (int ic0 = 0; ic0 < EMBED; ic0 += 4) {
        float w36[36];
        {
            const float4* wp = reinterpret_cast<const float4*>(cwr + ic0 * 9);
            #pragma unroll
            for (int q = 0; q < 9; q++) {
                float4 v = __ldg(wp + q);
                w36[4*q] = v.x; w36[4*q+1] = v.y; w36[4*q+2] = v.z; w36[4*q+3] = v.w;
            }
        }

        #pragma unroll
        for (int i4 = 0; i4 < 4; i4++) {
            const int ic = ic0 + i4;
            const float* w_r = w36 + i4 * 9;

            float se_r[56];
            const float4* rowp = reinterpret_cast<const float4*>(se_t + ic * SEROW);
            #pragma unroll
            for (int q = 0; q < 14; q++) {
                float4 v = rowp[q];
                se_r[4*q] = v.x; se_r[4*q+1] = v.y; se_r[4*q+2] = v.z; se_r[4*q+3] = v.w;
            }

            #pragma unroll
            for (int j = 0; j < 24; j++) {
                float a = acc[j];
                #pragma unroll
                for (int k = 0; k < 9; k++) a = fmaf(se_r[2 * j + k], w_r[k], a);
                acc[j] = a;
            }
        }
    }

    const int g = ch >> 3, i = ch & 7;
    #pragma unroll
    for (int j = 0; j < 24; j++) {
        int l = l0 + j;
        float v = acc[j];
        v = v > 0.f ? v : 0.f;
        g_u[((size_t)(b * NROUTE) + g * LOUT + l) * CAPSD + i] = v;
    }
}

// ---------------- gen: recompute u_hat, store fp16, S0 partials ------------
__global__ __launch_bounds__(256, 2) void gen_kernel(const float* __restrict__ W)
{
    extern __shared__ float sm[];            // 2 x WTILE1
    __shared__ float su[BT][128];

    const int gx    = blockIdx.x;
    const int b0blk = blockIdx.y * BT;
    const int t     = threadIdx.x;
    const int warp  = t >> 5, lane = t & 31;
    const int qd    = warp >> 2;
    const int wq    = warp & 3;
    const int lane128 = wq * 32 + lane;
    const int rbase = gx * R_LOOP;

    const int v0 = lane128;
    const int v1 = 128 + lane128;
    const bool val1 = (v1 < 200);
    const int c0 = v0 >> 2;
    const int c1 = val1 ? (v1 >> 2) : 0;
    const int o40 = (v0 & 3) * 4;
    const int o41 = (v1 & 3) * 4;

    {
        int bk = t >> 5, f4 = t & 31;
        const float4* src = reinterpret_cast<const float4*>(
            g_u + ((size_t)((b0blk + bk) * NROUTE + rbase)) * CAPSD);
        reinterpret_cast<float4*>(su[bk])[f4] = src[f4];
    }

    float4 accA[4], accB[4];
    #pragma unroll
    for (int k = 0; k < 4; k++) {
        accA[k] = make_float4(0.f, 0.f, 0.f, 0.f);
        accB[k] = make_float4(0.f, 0.f, 0.f, 0.f);
    }

    for (int idx = t; idx < NCAPS * 32; idx += 256) {
        int c = idx >> 5, kk = idx & 31;
        const float* src = W + ((size_t)(c * NROUTE + rbase)) * 128 + kk * 4;
        float* dst = sm + c * WROW + kk * 4;
        uint32_t ds = (uint32_t)__cvta_generic_to_shared(dst);
        asm volatile("cp.async.ca.shared.global [%0], [%1], 16;\n" :: "r"(ds), "l"(src));
    }
    asm volatile("cp.async.commit_group;\n");

    for (int p = 0; p < R_LOOP; p++) {
        if (p + 1 < R_LOOP) {
            float* dstbase = sm + ((p + 1) & 1) * WTILE1;
            const int rp = rbase + p + 1;
            for (int idx = t; idx < NCAPS * 32; idx += 256) {
                int c = idx >> 5, kk = idx & 31;
                const float* src = W + ((size_t)(c * NROUTE + rp)) * 128 + kk * 4;
                float* dst = dstbase + c * WROW + kk * 4;
                uint32_t ds = (uint32_t)__cvta_generic_to_shared(dst);
                asm volatile("cp.async.ca.shared.global [%0], [%1], 16;\n" :: "r"(ds), "l"(src));
            }
            asm volatile("cp.async.commit_group;\n");
            asm volatile("cp.async.wait_group 1;\n");
        } else {
            asm volatile("cp.async.wait_group 0;\n");
        }
        __syncthreads();

        const float* wr = sm + (p & 1) * WTILE1;
        const int r = rbase + p;

        float u[4][8];
        #pragma unroll
        for (int k = 0; k < 4; k++) {
            const float4* up = reinterpret_cast<const float4*>(&su[qd * 4 + k][p * 8]);
            float4 a = up[0], b2 = up[1];
            u[k][0]=a.x; u[k][1]=a.y; u[k][2]=a.z; u[k][3]=a.w;
            u[k][4]=b2.x; u[k][5]=b2.y; u[k][6]=b2.z; u[k][7]=b2.w;
        }

        float4 uhA[4], uhB[4];
        {
            const float* wc = wr + c0 * WROW + o40;
            #pragma unroll
            for (int k = 0; k < 4; k++) uhA[k] = make_float4(0.f,0.f,0.f,0.f);
            #pragma unroll
            for (int i = 0; i < 8; i++) {
                float4 w4 = *reinterpret_cast<const float4*>(wc + i * 16);
                #pragma unroll
                for (int k = 0; k < 4; k++) {
                    uhA[k].x = fmaf(u[k][i], w4.x, uhA[k].x);
                    uhA[k].y = fmaf(u[k][i], w4.y, uhA[k].y);
                    uhA[k].z = fmaf(u[k][i], w4.z, uhA[k].z);
                    uhA[k].w = fmaf(u[k][i], w4.w, uhA[k].w);
                }
            }
        }
        {
            const float* wc = wr + c1 * WROW + o41;
            #pragma unroll
            for (int k = 0; k < 4; k++) uhB[k] = make_float4(0.f,0.f,0.f,0.f);
            #pragma unroll
            for (int i = 0; i < 8; i++) {
                float4 w4 = *reinterpret_cast<const float4*>(wc + i * 16);
                #pragma unroll
                for (int k = 0; k < 4; k++) {
                    uhB[k].x = fmaf(u[k][i], w4.x, uhB[k].x);
                    uhB[k].y = fmaf(u[k][i], w4.y, uhB[k].y);
                    uhB[k].z = fmaf(u[k][i], w4.z, uhB[k].z);
                    uhB[k].w = fmaf(u[k][i], w4.w, uhB[k].w);
                }
            }
        }

        #pragma unroll
        for (int k = 0; k < 4; k++) {
            size_t base = ((size_t)((b0blk + qd * 4 + k) * NROUTE) + r) * CO;
            *reinterpret_cast<uint2*>(g_uhat_h + base + 4 * (size_t)v0) = f4_to_h4(uhA[k]);
            if (val1)
                *reinterpret_cast<uint2*>(g_uhat_h + base + 4 * (size_t)v1) = f4_to_h4(uhB[k]);

            accA[k].x += uhA[k].x; accA[k].y += uhA[k].y;
            accA[k].z += uhA[k].z; accA[k].w += uhA[k].w;
            accB[k].x += uhB[k].x; accB[k].y += uhB[k].y;
            accB[k].z += uhB[k].z; accB[k].w += uhB[k].w;
        }
        __syncthreads();
    }

    #pragma unroll
    for (int k = 0; k < 4; k++) {
        int b = b0blk + qd * 4 + k;
        float* pb = g_Spart + ((size_t)b * GX + gx) * CO;
        *reinterpret_cast<float4*>(pb + 4 * v0) = accA[k];
        if (val1) *reinterpret_cast<float4*>(pb + 4 * v1) = accB[k];
    }
}

// ---------------- routing read pass (warp-autonomous, barrier-free) --------
__global__ __launch_bounds__(256) void route_read_kernel()
{
    const int gx   = blockIdx.x;
    const int warp = threadIdx.x >> 5, lane = threadIdx.x & 31;
    const int b    = blockIdx.y * 8 + warp;
    const int rbase = gx * R_LOOP;
    const bool v3 = (lane < 4);

    float vs[4][8];
    #pragma unroll
    for (int s = 0; s < 4; s++) {
        int p = s * 32 + lane;
        if (s < 3 || v3) {
            float4 a = *reinterpret_cast<const float4*>(g_vsum + b * CO + 8 * p);
            float4 c = *reinterpret_cast<const float4*>(g_vsum + b * CO + 8 * p + 4);
            vs[s][0]=a.x; vs[s][1]=a.y; vs[s][2]=a.z; vs[s][3]=a.w;
            vs[s][4]=c.x; vs[s][5]=c.y; vs[s][6]=c.z; vs[s][7]=c.w;
        } else {
            #pragma unroll
            for (int j = 0; j < 8; j++) vs[s][j] = 0.f;
        }
    }

    float acc[4][8];
    #pragma unroll
    for (int s = 0; s < 4; s++)
        #pragma unroll
        for (int j = 0; j < 8; j++) acc[s][j] = 0.f;

    const size_t row0 = ((size_t)b * NROUTE + rbase) * CO;
    uint4 cur[4], nxt[4];
    const uint4 zero4 = make_uint4(0u, 0u, 0u, 0u);
    #pragma unroll
    for (int s = 0; s < 4; s++) {
        int p = s * 32 + lane;
        cur[s] = (s < 3 || v3)
            ? *reinterpret_cast<const uint4*>(g_uhat_h + row0 + 8 * (size_t)p)
            : zero4;
    }

    for (int roff = 0; roff < R_LOOP; roff++) {
        if (roff + 1 < R_LOOP) {
            size_t rowN = row0 + (size_t)(roff + 1) * CO;
            #pragma unroll
            for (int s = 0; s < 4; s++) {
                int p = s * 32 + lane;
                nxt[s] = (s < 3 || v3)
                    ? *reinterpret_cast<const uint4*>(g_uhat_h + rowN + 8 * (size_t)p)
                    : zero4;
            }
        }

        float uh[4][8];
        #pragma unroll
        for (int s = 0; s < 4; s++) h8_to_f8(cur[s], uh[s]);

        float d[4];
        #pragma unroll
        for (int s = 0; s < 4; s++) {
            float pdot = uh[s][0] * vs[s][0];
            #pragma unroll
            for (int j = 1; j < 8; j++) pdot = fmaf(uh[s][j], vs[s][j], pdot);
            pdot += __shfl_xor_sync(0xffffffffu, pdot, 1);
            d[s] = pdot;
        }
        if (!v3) d[3] = -1e30f;

        float m = fmaxf(fmaxf(d[0], d[1]), fmaxf(d[2], d[3]));
        #pragma unroll
        for (int off = 16; off >= 1; off >>= 1)
            m = fmaxf(m, __shfl_xor_sync(0xffffffffu, m, off));
        float e0 = __expf(d[0] - m);
        float e1 = __expf(d[1] - m);
        float e2 = __expf(d[2] - m);
        float e3 = v3 ? __expf(d[3] - m) : 0.f;
        float z = e0 + e1 + e2 + e3;
        #pragma unroll
        for (int off = 16; off >= 1; off >>= 1)
            z += __shfl_xor_sync(0xffffffffu, z, off);
        float invZ = 2.f / z;

        float cf[4] = { e0 * invZ, e1 * invZ, e2 * invZ, e3 * invZ };
        #pragma unroll
        for (int s = 0; s < 4; s++)
            #pragma unroll
            for (int j = 0; j < 8; j++)
                acc[s][j] = fmaf(cf[s], uh[s][j], acc[s][j]);

        #pragma unroll
        for (int s = 0; s < 4; s++) cur[s] = nxt[s];
    }

    float* pb = g_Spart + ((size_t)b * GX + gx) * CO;
    #pragma unroll
    for (int s = 0; s < 4; s++) {
        int p = s * 32 + lane;
        if (s < 3 || v3) {
            *reinterpret_cast<float4*>(pb + 8 * p) =
                make_float4(acc[s][0], acc[s][1], acc[s][2], acc[s][3]);
            *reinterpret_cast<float4*>(pb + 8 * p + 4) =
                make_float4(acc[s][4], acc[s][5], acc[s][6], acc[s][7]);
        }
    }
}

// ---------------- coalesced gx-reduction: g_S = sum_gx g_Spart -------------
// grid (BATCH, 4), 200 threads. Warp reads contiguous 128B per gx step.
__global__ void spart_reduce_kernel()
{
    const int b = blockIdx.x;
    const int f = blockIdx.y * 200 + threadIdx.x;
    const float* base = g_Spart + (size_t)b * GX * CO + f;
    float s = 0.f;
    #pragma unroll 8
    for (int gx = 0; gx < GX; gx++) s += base[(size_t)gx * CO];
    g_S[b * CO + f] = s;
}

// ---------------- squash (from g_S): vsum = (add?vsum:0)+squash(s*mult) ----
__global__ __launch_bounds__(256) void squash_kernel(float mult, int add_mode)
{
    int idx = blockIdx.x * blockDim.x + threadIdx.x;   // 12800
    int q = idx & 3, bc = idx >> 2;
    int b = bc / NCAPS, c = bc - b * NCAPS;

    float4 s = *reinterpret_cast<const float4*>(g_S + b * CO + c * ODIM + q * 4);
    s.x *= mult; s.y *= mult; s.z *= mult; s.w *= mult;

    float n2 = s.x * s.x + s.y * s.y + s.z * s.z + s.w * s.w;
    n2 += __shfl_xor_sync(0xffffffffu, n2, 1);
    n2 += __shfl_xor_sync(0xffffffffu, n2, 2);
    float n = sqrtf(n2);
    float f = n2 / ((1.f + n2) * (n + 1e-8f));

    float* dst = g_vsum + b * CO + c * ODIM + q * 4;
    if (add_mode) {
        dst[0] += f * s.x; dst[1] += f * s.y; dst[2] += f * s.z; dst[3] += f * s.w;
    } else {
        dst[0] = f * s.x; dst[1] = f * s.y; dst[2] = f * s.z; dst[3] = f * s.w;
    }
}

// ---------------- final: squash(g_S), lengths, argmax + fused MLP layer 1 --
__global__ void final_kernel(float* __restrict__ out,
                             const float* __restrict__ w1, const float* __restrict__ b1)
{
    __shared__ float v_s[NCAPS * ODIM];
    __shared__ float len_s[NCAPS];
    __shared__ int am_s;

    const int b = blockIdx.x, t = threadIdx.x;
    if (t < 200) {
        const unsigned mask = ((t >> 5) == 6) ? 0xffu : 0xffffffffu;
        int c = t >> 2, q = t & 3;
        float4 s = *reinterpret_cast<const float4*>(g_S + b * CO + c * ODIM + q * 4);
        float n2 = s.x * s.x + s.y * s.y + s.z * s.z + s.w * s.w;
        n2 += __shfl_xor_sync(mask, n2, 1);
        n2 += __shfl_xor_sync(mask, n2, 2);
        float n = sqrtf(n2);
        float f = n2 / ((1.f + n2) * (n + 1e-8f));
        float* vd = v_s + c * ODIM + q * 4;
        vd[0] = f * s.x; vd[1] = f * s.y; vd[2] = f * s.z; vd[3] = f * s.w;
        if (q == 0) {
            float len = f * n;
            len_s[c] = len;
            out[b * NCAPS + c] = len;
        }
    }
    __syncthreads();
    if (t == 0) {
        int best = 0; float bl = len_s[0];
        for (int c = 1; c < NCAPS; c++) if (len_s[c] > bl) { bl = len_s[c]; best = c; }
        am_s = best;
    }
    __syncthreads();

    const int row0 = am_s * ODIM;
    #pragma unroll
    for (int h = 0; h < 2; h++) {
        int n = h * 256 + t;
        float acc = b1[n];
        #pragma unroll
        for (int o = 0; o < 16; o++)
            acc = fmaf(v_s[row0 + o], w1[(row0 + o) * HID1 + n], acc);
        g_h1[b * HID1 + n] = acc > 0.f ? acc : 0.f;
    }
}

// ---------------- MLP layer 2 ----------------------------------------------
__global__ __launch_bounds__(256) void mlp2_kernel(const float* __restrict__ w2,
                                                   const float* __restrict__ b2)
{
    __shared__ float h1s[8 * HID1];
    const int t = threadIdx.x;
    const int n = blockIdx.x * 256 + t;
    const int bb = blockIdx.y * 8;
    for (int f = t; f < 8 * HID1; f += 256) {
        int b8 = f >> 9, k = f & 511;
        h1s[f] = g_h1[(bb + b8) * HID1 + k];
    }
    __syncthreads();
    float acc[8];
    float bias = b2[n];
    #pragma unroll
    for (int b8 = 0; b8 < 8; b8++) acc[b8] = bias;
    #pragma unroll 4
    for (int k = 0; k < HID1; k++) {
        float w = w2[(size_t)k * HID2 + n];
        #pragma unroll
        for (int b8 = 0; b8 < 8; b8++) acc[b8] = fmaf(h1s[b8 * HID1 + k], w, acc[b8]);
    }
    #pragma unroll
    for (int b8 = 0; b8 < 8; b8++) {
        float v = acc[b8];
        g_h2[(bb + b8) * HID2 + n] = v > 0.f ? v : 0.f;
    }
}

// ---------------- MLP layer 3 + sigmoid -> recon ---------------------------
// grid (38, 4), 256 threads, 64 KB smem. Thread: 2 n-outputs x 16 batches.
// Weight loads software-pipelined one k-step ahead.
__global__ __launch_bounds__(256) void mlp3_kernel(const float* __restrict__ w3,
                                                   const float* __restrict__ b3,
                                                   float* __restrict__ recon)
{
    extern __shared__ float h2s[];   // [16][1024]
    const int t = threadIdx.x;
    const int n0r = blockIdx.x * 512 + t;
    const int n1r = n0r + 256;
    const int bb = blockIdx.y * 16;
    {
        const float4* src = reinterpret_cast<const float4*>(g_h2 + bb * HID2);
        float4* dst = reinterpret_cast<float4*>(h2s);
        for (int f = t; f < 16 * HID2 / 4; f += 256) dst[f] = src[f];
    }
    __syncthreads();

    const bool ok0 = (n0r < NOUT), ok1 = (n1r < NOUT);
    const int n0 = ok0 ? n0r : (NOUT - 1);
    const int n1 = ok1 ? n1r : (NOUT - 1);

    float acc0[16], acc1[16];
    {
        float bias0 = b3[n0], bias1 = b3[n1];
        #pragma unroll
        for (int b16 = 0; b16 < 16; b16++) { acc0[b16] = bias0; acc1[b16] = bias1; }
    }

    // prologue: load k-step 0 weights
    float wa[4], wb[4];
    {
        const float* w3k = w3;
        wa[0] = w3k[n0];            wb[0] = w3k[n1];
        wa[1] = w3k[NOUT + n0];     wb[1] = w3k[NOUT + n1];
        wa[2] = w3k[2 * NOUT + n0]; wb[2] = w3k[2 * NOUT + n1];
        wa[3] = w3k[3 * NOUT + n0]; wb[3] = w3k[3 * NOUT + n1];
    }

    for (int k0 = 0; k0 < HID2; k0 += 4) {
        float na[4], nb[4];
        if (k0 + 4 < HID2) {
            const float* w3n = w3 + (size_t)(k0 + 4) * NOUT;
            na[0] = w3n[n0];            nb[0] = w3n[n1];
            na[1] = w3n[NOUT + n0];     nb[1] = w3n[NOUT + n1];
            na[2] = w3n[2 * NOUT + n0]; nb[2] = w3n[2 * NOUT + n1];
            na[3] = w3n[3 * NOUT + n0]; nb[3] = w3n[3 * NOUT + n1];
        }
        #pragma unroll
        for (int b16 = 0; b16 < 16; b16++) {
            float4 h = *reinterpret_cast<const float4*>(&h2s[b16 * HID2 + k0]);
            float a0 = acc0[b16], a1 = acc1[b16];
            a0 = fmaf(h.x, wa[0], a0); a1 = fmaf(h.x, wb[0], a1);
            a0 = fmaf(h.y, wa[1], a0); a1 = fmaf(h.y, wb[1], a1);
            a0 = fmaf(h.z, wa[2], a0); a1 = fmaf(h.z, wb[2], a1);
            a0 = fmaf(h.w, wa[3], a0); a1 = fmaf(h.w, wb[3], a1);
            acc0[b16] = a0; acc1[b16] = a1;
        }
        #pragma unroll
        for (int q = 0; q < 4; q++) { wa[q] = na[q]; wb[q] = nb[q]; }
    }
    #pragma unroll
    for (int b16 = 0; b16 < 16; b16++) {
        if (ok0) recon[(size_t)(bb + b16) * NOUT + n0r] = 1.f / (1.f + __expf(-acc0[b16]));
        if (ok1) recon[(size_t)(bb + b16) * NOUT + n1r] = 1.f / (1.f + __expf(-acc1[b16]));
    }
}

// ---------------- launch ----------------------------------------------------
extern "C" void kernel_launch(void* const* d_in, const int* in_sizes, int n_in,
                              void* d_out, int out_size)
{
    const int*   x      = (const int*)  d_in[0];
    const float* emb    = (const float*)d_in[1];
    const float* conv_w = (const float*)d_in[2];
    const float* conv_b = (const float*)d_in[3];
    const float* W      = (const float*)d_in[4];
    const float* w1     = (const float*)d_in[5];
    const float* b1     = (const float*)d_in[6];
    const float* w2     = (const float*)d_in[7];
    const float* b2     = (const float*)d_in[8];
    const float* w3     = (const float*)d_in[9];
    const float* b3     = (const float*)d_in[10];
    float* out = (float*)d_out;
    float* recon = out + ((size_t)out_size - (size_t)BATCH * NOUT);

    const int gen_smem = GEN_SMEM_FLOATS * (int)sizeof(float);   // 57.6 KB

    static int attr_done = 0;
    if (!attr_done) {
        cudaFuncSetAttribute(mlp3_kernel, cudaFuncAttributeMaxDynamicSharedMemorySize,
                             16 * HID2 * sizeof(float));
        cudaFuncSetAttribute(gen_kernel, cudaFuncAttributeMaxDynamicSharedMemorySize,
                             gen_smem);
        attr_done = 1;
    }

    // 1. conv/embed -> u
    conv_embed_kernel<<<dim3(4, BATCH), 256>>>(x, emb, conv_w, conv_b);

    // 2. gen: u_hat fp16 + S0 partials (2 CTAs/SM)
    gen_kernel<<<dim3(GX, BATCH / BT), 256, gen_smem>>>(W);

    // 3. reduce partials; v0 = squash(S0/50); vsum = v0
    spart_reduce_kernel<<<dim3(BATCH, 4), 200>>>();
    squash_kernel<<<(BATCH * NCAPS * 4) / 256, 256>>>(1.f / (float)NCAPS, 0);

    // 4. pass 1: s1 partials (softmax vs v0)
    route_read_kernel<<<dim3(GX, BATCH / 8), 256>>>();

    // 5. reduce; v1 = squash(s1); vsum += v1
    spart_reduce_kernel<<<dim3(BATCH, 4), 200>>>();
    squash_kernel<<<(BATCH * NCAPS * 4) / 256, 256>>>(1.f, 1);

    // 6. pass 2: s2 partials (softmax vs v0+v1)
    route_read_kernel<<<dim3(GX, BATCH / 8), 256>>>();

    // 7. reduce; final v, lengths, argmax + MLP layer 1
    spart_reduce_kernel<<<dim3(BATCH, 4), 200>>>();
    final_kernel<<<BATCH, 256>>>(out, w1, b1);

    // 8. MLP layers 2,3 + sigmoid
    mlp2_kernel<<<dim3(HID2 / 256, BATCH / 8), 256>>>(w2, b2);
    mlp3_kernel<<<dim3((NOUT + 511) / 512, BATCH / 16), 256,
                 16 * HID2 * sizeof(float)>>>(w3, b3, recon);
}

// round 17
// speedup vs baseline: 2.0906x; 1.0152x over previous
#include <cuda_runtime.h>
#include <cuda_fp16.h>
#include <math.h>
#include <stdint.h>

// ---------------- problem constants ----------------
#define BATCH   64
#define SEQ     200
#define EMBED   64
#define VOCAB   95
#define LOUT    96
#define NCAPS   50
#define CAPSD   8
#define ODIM    16
#define NROUTE  3072
#define HID1    512
#define HID2    1024
#define NOUT    19000
#define CO      (NCAPS*ODIM)     // 800

// routing tiling
#define R_LOOP   16
#define GX       (NROUTE/R_LOOP)        // 192
#define BT       8                      // batches per block (2 quads x 4)
#define WROW     144                    // padded row (conflict-free LDS.128)
#define WTILE1   (NCAPS*WROW)           // 7200 floats per single-route tile
#define GEN_SMEM_FLOATS (2*WTILE1)      // 57.6 KB dynamic

// ---------------- device scratch ----------------
__device__ float  g_u[BATCH * NROUTE * CAPSD];             // 6.3 MB
__device__ __half g_uhat_h[(size_t)BATCH * NROUTE * CO];   // 315 MB fp16 u_hat
__device__ float  g_Spart[(size_t)BATCH * GX * CO];        // [b][gx][CO] 39.3 MB
__device__ float  g_S[BATCH * CO];
__device__ float  g_vsum[BATCH * CO];
__device__ float  g_h1[BATCH * HID1];
__device__ float  g_h2[BATCH * HID2];

// ---------------- half conversions ----------------
__device__ __forceinline__ uint2 f4_to_h4(float4 v) {
    __half2 h0 = __floats2half2_rn(v.x, v.y);
    __half2 h1 = __floats2half2_rn(v.z, v.w);
    uint2 r;
    r.x = *reinterpret_cast<uint32_t*>(&h0);
    r.y = *reinterpret_cast<uint32_t*>(&h1);
    return r;
}
__device__ __forceinline__ void h8_to_f8(uint4 r, float* f) {
    __half2 h0 = *reinterpret_cast<__half2*>(&r.x);
    __half2 h1 = *reinterpret_cast<__half2*>(&r.y);
    __half2 h2 = *reinterpret_cast<__half2*>(&r.z);
    __half2 h3 = *reinterpret_cast<__half2*>(&r.w);
    float2 a = __half22float2(h0), b = __half22float2(h1);
    float2 c = __half22float2(h2), d = __half22float2(h3);
    f[0]=a.x; f[1]=a.y; f[2]=b.x; f[3]=b.y;
    f[4]=c.x; f[5]=c.y; f[6]=d.x; f[7]=d.y;
}

// ---------------- kernel 1: embedding + conv1d + relu -> u ----------------
#define SEROW 60
__global__ __launch_bounds__(256, 2) void conv_embed_kernel(
    const int* __restrict__ x, const float* __restrict__ emb,
    const float* __restrict__ cw, const float* __restrict__ cb)
{
    __shared__ int   xs[56];
    __shared__ float se_t[EMBED * SEROW];

    const int l0 = blockIdx.x * 24;
    const int b  = blockIdx.y;
    const int t  = threadIdx.x;

    if (t < 55) xs[t] = x[b * SEQ + 2 * l0 + t];
    __syncthreads();
    for (int f = t; f < 55 * EMBED; f += 256) {
        int s = f >> 6, ic = f & 63;
        se_t[ic * SEROW + s] = emb[xs[s] * EMBED + ic];
    }
    __syncthreads();

    const int ch = t;
    float acc[24];
    {
        float bias = cb[ch];
        #pragma unroll
        for (int j = 0; j < 24; j++) acc[j] = bias;
    }

    const float* cwr = cw + (size_t)ch * (EMBED * 9);
    for (int ic0 = 0; ic0 < EMBED; ic0 += 4) {
        float w36[36];
        {
            const float4* wp = reinterpret_cast<const float4*>(cwr + ic0 * 9);
            #pragma unroll
            for (int q = 0; q < 9; q++) {
                float4 v = __ldg(wp + q);
                w36[4*q] = v.x; w36[4*q+1] = v.y; w36[4*q+2] = v.z; w36[4*q+3] = v.w;
            }
        }

        #pragma unroll
        for (int i4 = 0; i4 < 4; i4++) {
            const int ic = ic0 + i4;
            const float* w_r = w36 + i4 * 9;

            float se_r[56];
            const float4* rowp = reinterpret_cast<const float4*>(se_t + ic * SEROW);
            #pragma unroll
            for (int q = 0; q < 14; q++) {
                float4 v = rowp[q];
                se_r[4*q] = v.x; se_r[4*q+1] = v.y; se_r[4*q+2] = v.z; se_r[4*q+3] = v.w;
            }

            #pragma unroll
            for (int j = 0; j < 24; j++) {
                float a = acc[j];
                #pragma unroll
                for (int k = 0; k < 9; k++) a = fmaf(se_r[2 * j + k], w_r[k], a);
                acc[j] = a;
            }
        }
    }

    const int g = ch >> 3, i = ch & 7;
    #pragma unroll
    for (int j = 0; j < 24; j++) {
        int l = l0 + j;
        float v = acc[j];
        v = v > 0.f ? v : 0.f;
        g_u[((size_t)(b * NROUTE) + g * LOUT + l) * CAPSD + i] = v;
    }
}

// ---------------- gen: recompute u_hat, store fp16, S0 partials ------------
// Slot B fully skipped by invalid lanes (warp wq=3 skips branch-uniformly).
__global__ __launch_bounds__(256, 2) void gen_kernel(const float* __restrict__ W)
{
    extern __shared__ float sm[];            // 2 x WTILE1
    __shared__ float su[BT][128];

    const int gx    = blockIdx.x;
    const int b0blk = blockIdx.y * BT;
    const int t     = threadIdx.x;
    const int warp  = t >> 5, lane = t & 31;
    const int qd    = warp >> 2;
    const int wq    = warp & 3;
    const int lane128 = wq * 32 + lane;
    const int rbase = gx * R_LOOP;

    const int v0 = lane128;
    const int v1 = 128 + lane128;
    const bool val1 = (v1 < 200);
    const int c0 = v0 >> 2;
    const int c1 = v1 >> 2;                  // used only when val1
    const int o40 = (v0 & 3) * 4;
    const int o41 = (v1 & 3) * 4;

    {
        int bk = t >> 5, f4 = t & 31;
        const float4* src = reinterpret_cast<const float4*>(
            g_u + ((size_t)((b0blk + bk) * NROUTE + rbase)) * CAPSD);
        reinterpret_cast<float4*>(su[bk])[f4] = src[f4];
    }

    float4 accA[4], accB[4];
    #pragma unroll
    for (int k = 0; k < 4; k++) {
        accA[k] = make_float4(0.f, 0.f, 0.f, 0.f);
        accB[k] = make_float4(0.f, 0.f, 0.f, 0.f);
    }

    for (int idx = t; idx < NCAPS * 32; idx += 256) {
        int c = idx >> 5, kk = idx & 31;
        const float* src = W + ((size_t)(c * NROUTE + rbase)) * 128 + kk * 4;
        float* dst = sm + c * WROW + kk * 4;
        uint32_t ds = (uint32_t)__cvta_generic_to_shared(dst);
        asm volatile("cp.async.ca.shared.global [%0], [%1], 16;\n" :: "r"(ds), "l"(src));
    }
    asm volatile("cp.async.commit_group;\n");

    for (int p = 0; p < R_LOOP; p++) {
        if (p + 1 < R_LOOP) {
            float* dstbase = sm + ((p + 1) & 1) * WTILE1;
            const int rp = rbase + p + 1;
            for (int idx = t; idx < NCAPS * 32; idx += 256) {
                int c = idx >> 5, kk = idx & 31;
                const float* src = W + ((size_t)(c * NROUTE + rp)) * 128 + kk * 4;
                float* dst = dstbase + c * WROW + kk * 4;
                uint32_t ds = (uint32_t)__cvta_generic_to_shared(dst);
                asm volatile("cp.async.ca.shared.global [%0], [%1], 16;\n" :: "r"(ds), "l"(src));
            }
            asm volatile("cp.async.commit_group;\n");
            asm volatile("cp.async.wait_group 1;\n");
        } else {
            asm volatile("cp.async.wait_group 0;\n");
        }
        __syncthreads();

        const float* wr = sm + (p & 1) * WTILE1;
        const int r = rbase + p;

        float u[4][8];
        #pragma unroll
        for (int k = 0; k < 4; k++) {
            const float4* up = reinterpret_cast<const float4*>(&su[qd * 4 + k][p * 8]);
            float4 a = up[0], b2 = up[1];
            u[k][0]=a.x; u[k][1]=a.y; u[k][2]=a.z; u[k][3]=a.w;
            u[k][4]=b2.x; u[k][5]=b2.y; u[k][6]=b2.z; u[k][7]=b2.w;
        }

        // slot A (always valid)
        float4 uhA[4];
        {
            const float* wc = wr + c0 * WROW + o40;
            #pragma unroll
            for (int k = 0; k < 4; k++) uhA[k] = make_float4(0.f,0.f,0.f,0.f);
            #pragma unroll
            for (int i = 0; i < 8; i++) {
                float4 w4 = *reinterpret_cast<const float4*>(wc + i * 16);
                #pragma unroll
                for (int k = 0; k < 4; k++) {
                    uhA[k].x = fmaf(u[k][i], w4.x, uhA[k].x);
                    uhA[k].y = fmaf(u[k][i], w4.y, uhA[k].y);
                    uhA[k].z = fmaf(u[k][i], w4.z, uhA[k].z);
                    uhA[k].w = fmaf(u[k][i], w4.w, uhA[k].w);
                }
            }
        }
        #pragma unroll
        for (int k = 0; k < 4; k++) {
            size_t base = ((size_t)((b0blk + qd * 4 + k) * NROUTE) + r) * CO;
            *reinterpret_cast<uint2*>(g_uhat_h + base + 4 * (size_t)v0) = f4_to_h4(uhA[k]);
            accA[k].x += uhA[k].x; accA[k].y += uhA[k].y;
            accA[k].z += uhA[k].z; accA[k].w += uhA[k].w;
        }

        // slot B (only valid lanes compute; warp wq=3 skips entirely)
        if (val1) {
            float4 uhB[4];
            const float* wc = wr + c1 * WROW + o41;
            #pragma unroll
            for (int k = 0; k < 4; k++) uhB[k] = make_float4(0.f,0.f,0.f,0.f);
            #pragma unroll
            for (int i = 0; i < 8; i++) {
                float4 w4 = *reinterpret_cast<const float4*>(wc + i * 16);
                #pragma unroll
                for (int k = 0; k < 4; k++) {
                    uhB[k].x = fmaf(u[k][i], w4.x, uhB[k].x);
                    uhB[k].y = fmaf(u[k][i], w4.y, uhB[k].y);
                    uhB[k].z = fmaf(u[k][i], w4.z, uhB[k].z);
                    uhB[k].w = fmaf(u[k][i], w4.w, uhB[k].w);
                }
            }
            #pragma unroll
            for (int k = 0; k < 4; k++) {
                size_t base = ((size_t)((b0blk + qd * 4 + k) * NROUTE) + r) * CO;
                *reinterpret_cast<uint2*>(g_uhat_h + base + 4 * (size_t)v1) = f4_to_h4(uhB[k]);
                accB[k].x += uhB[k].x; accB[k].y += uhB[k].y;
                accB[k].z += uhB[k].z; accB[k].w += uhB[k].w;
            }
        }
        __syncthreads();
    }

    #pragma unroll
    for (int k = 0; k < 4; k++) {
        int b = b0blk + qd * 4 + k;
        float* pb = g_Spart + ((size_t)b * GX + gx) * CO;
        *reinterpret_cast<float4*>(pb + 4 * v0) = accA[k];
        if (val1) *reinterpret_cast<float4*>(pb + 4 * v1) = accB[k];
    }
}

// ---------------- routing read pass (warp-autonomous, barrier-free) --------
__global__ __launch_bounds__(256) void route_read_kernel()
{
    const int gx   = blockIdx.x;
    const int warp = threadIdx.x >> 5, lane = threadIdx.x & 31;
    const int b    = blockIdx.y * 8 + warp;
    const int rbase = gx * R_LOOP;
    const bool v3 = (lane < 4);

    float vs[4][8];
    #pragma unroll
    for (int s = 0; s < 4; s++) {
        int p = s * 32 + lane;
        if (s < 3 || v3) {
            float4 a = *reinterpret_cast<const float4*>(g_vsum + b * CO + 8 * p);
            float4 c = *reinterpret_cast<const float4*>(g_vsum + b * CO + 8 * p + 4);
            vs[s][0]=a.x; vs[s][1]=a.y; vs[s][2]=a.z; vs[s][3]=a.w;
            vs[s][4]=c.x; vs[s][5]=c.y; vs[s][6]=c.z; vs[s][7]=c.w;
        } else {
            #pragma unroll
            for (int j = 0; j < 8; j++) vs[s][j] = 0.f;
        }
    }

    float acc[4][8];
    #pragma unroll
    for (int s = 0; s < 4; s++)
        #pragma unroll
        for (int j = 0; j < 8; j++) acc[s][j] = 0.f;

    const size_t row0 = ((size_t)b * NROUTE + rbase) * CO;
    uint4 cur[4], nxt[4];
    const uint4 zero4 = make_uint4(0u, 0u, 0u, 0u);
    #pragma unroll
    for (int s = 0; s < 4; s++) {
        int p = s * 32 + lane;
        cur[s] = (s < 3 || v3)
            ? *reinterpret_cast<const uint4*>(g_uhat_h + row0 + 8 * (size_t)p)
            : zero4;
    }

    for (int roff = 0; roff < R_LOOP; roff++) {
        if (roff + 1 < R_LOOP) {
            size_t rowN = row0 + (size_t)(roff + 1) * CO;
            #pragma unroll
            for (int s = 0; s < 4; s++) {
                int p = s * 32 + lane;
                nxt[s] = (s < 3 || v3)
                    ? *reinterpret_cast<const uint4*>(g_uhat_h + rowN + 8 * (size_t)p)
                    : zero4;
            }
        }

        float uh[4][8];
        #pragma unroll
        for (int s = 0; s < 4; s++) h8_to_f8(cur[s], uh[s]);

        float d[4];
        #pragma unroll
        for (int s = 0; s < 4; s++) {
            float pdot = uh[s][0] * vs[s][0];
            #pragma unroll
            for (int j = 1; j < 8; j++) pdot = fmaf(uh[s][j], vs[s][j], pdot);
            pdot += __shfl_xor_sync(0xffffffffu, pdot, 1);
            d[s] = pdot;
        }
        if (!v3) d[3] = -1e30f;

        float m = fmaxf(fmaxf(d[0], d[1]), fmaxf(d[2], d[3]));
        #pragma unroll
        for (int off = 16; off >= 1; off >>= 1)
            m = fmaxf(m, __shfl_xor_sync(0xffffffffu, m, off));
        float e0 = __expf(d[0] - m);
        float e1 = __expf(d[1] - m);
        float e2 = __expf(d[2] - m);
        float e3 = v3 ? __expf(d[3] - m) : 0.f;
        float z = e0 + e1 + e2 + e3;
        #pragma unroll
        for (int off = 16; off >= 1; off >>= 1)
            z += __shfl_xor_sync(0xffffffffu, z, off);
        float invZ = 2.f / z;

        float cf[4] = { e0 * invZ, e1 * invZ, e2 * invZ, e3 * invZ };
        #pragma unroll
        for (int s = 0; s < 4; s++)
            #pragma unroll
            for (int j = 0; j < 8; j++)
                acc[s][j] = fmaf(cf[s], uh[s][j], acc[s][j]);

        #pragma unroll
        for (int s = 0; s < 4; s++) cur[s] = nxt[s];
    }

    float* pb = g_Spart + ((size_t)b * GX + gx) * CO;
    #pragma unroll
    for (int s = 0; s < 4; s++) {
        int p = s * 32 + lane;
        if (s < 3 || v3) {
            *reinterpret_cast<float4*>(pb + 8 * p) =
                make_float4(acc[s][0], acc[s][1], acc[s][2], acc[s][3]);
            *reinterpret_cast<float4*>(pb + 8 * p + 4) =
                make_float4(acc[s][4], acc[s][5], acc[s][6], acc[s][7]);
        }
    }
}

// ---------------- fused gx-reduce + squash (parallelism-preserving) --------
// grid (BATCH, 5), 160 threads. Warp = exactly 2 capsules; 16-lane norm
// via 4 convergent shuffles. Same 51K-thread sweep as spart_reduce.
__global__ void reduce_squash_kernel(float mult, int add_mode)
{
    const int b = blockIdx.x;
    const int f = blockIdx.y * 160 + threadIdx.x;   // 0..799
    const float* base = g_Spart + (size_t)b * GX * CO + f;
    float s = 0.f;
    #pragma unroll 8
    for (int gx = 0; gx < GX; gx++) s += base[(size_t)gx * CO];
    s *= mult;

    float n2 = s * s;
    n2 += __shfl_xor_sync(0xffffffffu, n2, 1);
    n2 += __shfl_xor_sync(0xffffffffu, n2, 2);
    n2 += __shfl_xor_sync(0xffffffffu, n2, 4);
    n2 += __shfl_xor_sync(0xffffffffu, n2, 8);
    float n = sqrtf(n2);
    float fac = n2 / ((1.f + n2) * (n + 1e-8f));
    float v = fac * s;

    float* dst = g_vsum + b * CO + f;
    *dst = add_mode ? (*dst + v) : v;
}

// ---------------- coalesced gx-reduction: g_S = sum_gx g_Spart -------------
__global__ void spart_reduce_kernel()
{
    const int b = blockIdx.x;
    const int f = blockIdx.y * 200 + threadIdx.x;
    const float* base = g_Spart + (size_t)b * GX * CO + f;
    float s = 0.f;
    #pragma unroll 8
    for (int gx = 0; gx < GX; gx++) s += base[(size_t)gx * CO];
    g_S[b * CO + f] = s;
}

// ---------------- final: squash(g_S), lengths, argmax + fused MLP layer 1 --
__global__ void final_kernel(float* __restrict__ out,
                             const float* __restrict__ w1, const float* __restrict__ b1)
{
    __shared__ float v_s[NCAPS * ODIM];
    __shared__ float len_s[NCAPS];
    __shared__ int am_s;

    const int b = blockIdx.x, t = threadIdx.x;
    if (t < 200) {
        const unsigned mask = ((t >> 5) == 6) ? 0xffu : 0xffffffffu;
        int c = t >> 2, q = t & 3;
        float4 s = *reinterpret_cast<const float4*>(g_S + b * CO + c * ODIM + q * 4);
        float n2 = s.x * s.x + s.y * s.y + s.z * s.z + s.w * s.w;
        n2 += __shfl_xor_sync(mask, n2, 1);
        n2 += __shfl_xor_sync(mask, n2, 2);
        float n = sqrtf(n2);
        float f = n2 / ((1.f + n2) * (n + 1e-8f));
        float* vd = v_s + c * ODIM + q * 4;
        vd[0] = f * s.x; vd[1] = f * s.y; vd[2] = f * s.z; vd[3] = f * s.w;
        if (q == 0) {
            float len = f * n;
            len_s[c] = len;
            out[b * NCAPS + c] = len;
        }
    }
    __syncthreads();
    if (t == 0) {
        int best = 0; float bl = len_s[0];
        for (int c = 1; c < NCAPS; c++) if (len_s[c] > bl) { bl = len_s[c]; best = c; }
        am_s = best;
    }
    __syncthreads();

    const int row0 = am_s * ODIM;
    #pragma unroll
    for (int h = 0; h < 2; h++) {
        int n = h * 256 + t;
        float acc = b1[n];
        #pragma unroll
        for (int o = 0; o < 16; o++)
            acc = fmaf(v_s[row0 + o], w1[(row0 + o) * HID1 + n], acc);
        g_h1[b * HID1 + n] = acc > 0.f ? acc : 0.f;
    }
}

// ---------------- MLP layer 2 ----------------------------------------------
__global__ __launch_bounds__(256) void mlp2_kernel(const float* __restrict__ w2,
                                                   const float* __restrict__ b2)
{
    __shared__ float h1s[8 * HID1];
    const int t = threadIdx.x;
    const int n = blockIdx.x * 256 + t;
    const int bb = blockIdx.y * 8;
    for (int f = t; f < 8 * HID1; f += 256) {
        int b8 = f >> 9, k = f & 511;
        h1s[f] = g_h1[(bb + b8) * HID1 + k];
    }
    __syncthreads();
    float acc[8];
    float bias = b2[n];
    #pragma unroll
    for (int b8 = 0; b8 < 8; b8++) acc[b8] = bias;
    #pragma unroll 4
    for (int k = 0; k < HID1; k++) {
        float w = w2[(size_t)k * HID2 + n];
        #pragma unroll
        for (int b8 = 0; b8 < 8; b8++) acc[b8] = fmaf(h1s[b8 * HID1 + k], w, acc[b8]);
    }
    #pragma unroll
    for (int b8 = 0; b8 < 8; b8++) {
        float v = acc[b8];
        g_h2[(bb + b8) * HID2 + n] = v > 0.f ? v : 0.f;
    }
}

// ---------------- MLP layer 3 + sigmoid -> recon ---------------------------
__global__ __launch_bounds__(256) void mlp3_kernel(const float* __restrict__ w3,
                                                   const float* __restrict__ b3,
                                                   float* __restrict__ recon)
{
    extern __shared__ float h2s[];   // [16][1024]
    const int t = threadIdx.x;
    const int n0r = blockIdx.x * 512 + t;
    const int n1r = n0r + 256;
    const int bb = blockIdx.y * 16;
    {
        const float4* src = reinterpret_cast<const float4*>(g_h2 + bb * HID2);
        float4* dst = reinterpret_cast<float4*>(h2s);
        for (int f = t; f < 16 * HID2 / 4; f += 256) dst[f] = src[f];
    }
    __syncthreads();

    const bool ok0 = (n0r < NOUT), ok1 = (n1r < NOUT);
    const int n0 = ok0 ? n0r : (NOUT - 1);
    const int n1 = ok1 ? n1r : (NOUT - 1);

    float acc0[16], acc1[16];
    {
        float bias0 = b3[n0], bias1 = b3[n1];
        #pragma unroll
        for (int b16 = 0; b16 < 16; b16++) { acc0[b16] = bias0; acc1[b16] = bias1; }
    }

    float wa[4], wb[4];
    {
        const float* w3k = w3;
        wa[0] = w3k[n0];            wb[0] = w3k[n1];
        wa[1] = w3k[NOUT + n0];     wb[1] = w3k[NOUT + n1];
        wa[2] = w3k[2 * NOUT + n0]; wb[2] = w3k[2 * NOUT + n1];
        wa[3] = w3k[3 * NOUT + n0]; wb[3] = w3k[3 * NOUT + n1];
    }

    for (int k0 = 0; k0 < HID2; k0 += 4) {
        float na[4], nb[4];
        if (k0 + 4 < HID2) {
            const float* w3n = w3 + (size_t)(k0 + 4) * NOUT;
            na[0] = w3n[n0];            nb[0] = w3n[n1];
            na[1] = w3n[NOUT + n0];     nb[1] = w3n[NOUT + n1];
            na[2] = w3n[2 * NOUT + n0]; nb[2] = w3n[2 * NOUT + n1];
            na[3] = w3n[3 * NOUT + n0]; nb[3] = w3n[3 * NOUT + n1];
        }
        #pragma unroll
        for (int b16 = 0; b16 < 16; b16++) {
            float4 h = *reinterpret_cast<const float4*>(&h2s[b16 * HID2 + k0]);
            float a0 = acc0[b16], a1 = acc1[b16];
            a0 = fmaf(h.x, wa[0], a0); a1 = fmaf(h.x, wb[0], a1);
            a0 = fmaf(h.y, wa[1], a0); a1 = fmaf(h.y, wb[1], a1);
            a0 = fmaf(h.z, wa[2], a0); a1 = fmaf(h.z, wb[2], a1);
            a0 = fmaf(h.w, wa[3], a0); a1 = fmaf(h.w, wb[3], a1);
            acc0[b16] = a0; acc1[b16] = a1;
        }
        #pragma unroll
        for (int q = 0; q < 4; q++) { wa[q] = na[q]; wb[q] = nb[q]; }
    }
    #pragma unroll
    for (int b16 = 0; b16 < 16; b16++) {
        if (ok0) recon[(size_t)(bb + b16) * NOUT + n0r] = 1.f / (1.f + __expf(-acc0[b16]));
        if (ok1) recon[(size_t)(bb + b16) * NOUT + n1r] = 1.f / (1.f + __expf(-acc1[b16]));
    }
}

// ---------------- launch ----------------------------------------------------
extern "C" void kernel_launch(void* const* d_in, const int* in_sizes, int n_in,
                              void* d_out, int out_size)
{
    const int*   x      = (const int*)  d_in[0];
    const float* emb    = (const float*)d_in[1];
    const float* conv_w = (const float*)d_in[2];
    const float* conv_b = (const float*)d_in[3];
    const float* W      = (const float*)d_in[4];
    const float* w1     = (const float*)d_in[5];
    const float* b1     = (const float*)d_in[6];
    const float* w2     = (const float*)d_in[7];
    const float* b2     = (const float*)d_in[8];
    const float* w3     = (const float*)d_in[9];
    const float* b3     = (const float*)d_in[10];
    float* out = (float*)d_out;
    float* recon = out + ((size_t)out_size - (size_t)BATCH * NOUT);

    const int gen_smem = GEN_SMEM_FLOATS * (int)sizeof(float);   // 57.6 KB

    static int attr_done = 0;
    if (!attr_done) {
        cudaFuncSetAttribute(mlp3_kernel, cudaFuncAttributeMaxDynamicSharedMemorySize,
                             16 * HID2 * sizeof(float));
        cudaFuncSetAttribute(gen_kernel, cudaFuncAttributeMaxDynamicSharedMemorySize,
                             gen_smem);
        attr_done = 1;
    }

    // 1. conv/embed -> u
    conv_embed_kernel<<<dim3(4, BATCH), 256>>>(x, emb, conv_w, conv_b);

    // 2. gen: u_hat fp16 + S0 partials (2 CTAs/SM)
    gen_kernel<<<dim3(GX, BATCH / BT), 256, gen_smem>>>(W);

    // 3. v0 = squash(reduce(S0)/50); vsum = v0 (fused, full parallelism)
    reduce_squash_kernel<<<dim3(BATCH, 5), 160>>>(1.f / (float)NCAPS, 0);

    // 4. pass 1: s1 partials (softmax vs v0)
    route_read_kernel<<<dim3(GX, BATCH / 8), 256>>>();

    // 5. v1 = squash(reduce(s1)); vsum += v1
    reduce_squash_kernel<<<dim3(BATCH, 5), 160>>>(1.f, 1);

    // 6. pass 2: s2 partials (softmax vs v0+v1)
    route_read_kernel<<<dim3(GX, BATCH / 8), 256>>>();

    // 7. reduce; final v, lengths, argmax + MLP layer 1
    spart_reduce_kernel<<<dim3(BATCH, 4), 200>>>();
    final_kernel<<<BATCH, 256>>>(out, w1, b1);

    // 8. MLP layers 2,3 + sigmoid
    mlp2_kernel<<<dim3(HID2 / 256, BATCH / 8), 256>>>(w2, b2);
    mlp3_kernel<<<dim3((NOUT + 511) / 512, BATCH / 16), 256,
                 16 * HID2 * sizeof(float)>>>(w3, b3, recon);
}